// round 9
// baseline (speedup 1.0000x reference)
#include <cuda_runtime.h>
#include <cuda_fp16.h>
#include <cstdint>

#define BB 16
#define CC 256
#define HH 96
#define WW 96
#define QKD 64
#define PP (HH*WW)          // 9216
#define JTOT 384

// ---------------- scratch (static device memory; no allocs allowed) ----------
__device__ float g_bcat[JTOT];
__device__ __half g_Whi[JTOT*CC];
__device__ __half g_Wlo[JTOT*CC];
__device__ __half g_Qhi[(size_t)BB*WW*HH*QKD];      // [b*w*h][q]
__device__ __half g_Qlo[(size_t)BB*WW*HH*QKD];
__device__ __half g_Khi[(size_t)BB*WW*HH*QKD];
__device__ __half g_Klo[(size_t)BB*WW*HH*QKD];
__device__ __half g_Vhi[(size_t)BB*WW*HH*CC];       // [b*w*g][c] single fp16
__device__ __half g_Ot[(size_t)BB*WW*HH*CC];        // [b][w][h][c]  fp16

// ---------------- PTX helpers (baseline, sm_103-safe) ------------------------
__device__ __forceinline__ uint32_t smem_u32(const void* p) {
    uint32_t a;
    asm("{ .reg .u64 t; cvta.to.shared.u64 t, %1; cvt.u32.u64 %0, t; }" : "=r"(a) : "l"(p));
    return a;
}
__device__ __forceinline__ void ldsm_x4(uint32_t* r, uint32_t addr) {
    asm volatile("ldmatrix.sync.aligned.m8n8.x4.shared.b16 {%0,%1,%2,%3}, [%4];"
        : "=r"(r[0]), "=r"(r[1]), "=r"(r[2]), "=r"(r[3]) : "r"(addr));
}
__device__ __forceinline__ void ldsm_x2(uint32_t* r, uint32_t addr) {
    asm volatile("ldmatrix.sync.aligned.m8n8.x2.shared.b16 {%0,%1}, [%2];"
        : "=r"(r[0]), "=r"(r[1]) : "r"(addr));
}
__device__ __forceinline__ void ldsm_x2t(uint32_t* r, uint32_t addr) {
    asm volatile("ldmatrix.sync.aligned.m8n8.x2.trans.shared.b16 {%0,%1}, [%2];"
        : "=r"(r[0]), "=r"(r[1]) : "r"(addr));
}
__device__ __forceinline__ void mma_h(float* d, const uint32_t* a, const uint32_t* b) {
    asm volatile("mma.sync.aligned.m16n8k16.row.col.f32.f16.f16.f32 "
        "{%0,%1,%2,%3}, {%4,%5,%6,%7}, {%8,%9}, {%0,%1,%2,%3};"
        : "+f"(d[0]), "+f"(d[1]), "+f"(d[2]), "+f"(d[3])
        : "r"(a[0]), "r"(a[1]), "r"(a[2]), "r"(a[3]), "r"(b[0]), "r"(b[1]));
}
__device__ __forceinline__ void cvt_hilo_h(float4 v, uint2& hi, uint2& lo) {
    __half2 h0 = __float22half2_rn(make_float2(v.x, v.y));
    __half2 h1 = __float22half2_rn(make_float2(v.z, v.w));
    float2 f0 = __half22float2(h0), f1 = __half22float2(h1);
    __half2 l0 = __float22half2_rn(make_float2(v.x - f0.x, v.y - f0.y));
    __half2 l1 = __float22half2_rn(make_float2(v.z - f1.x, v.w - f1.y));
    hi = make_uint2(*(uint32_t*)&h0, *(uint32_t*)&h1);
    lo = make_uint2(*(uint32_t*)&l0, *(uint32_t*)&l1);
}
#define CP_ASYNC16(dst, src) \
    asm volatile("cp.async.cg.shared.global [%0], [%1], 16;" :: "r"(dst), "l"(src))
#define CP_COMMIT() asm volatile("cp.async.commit_group;" ::: "memory")
#define CP_WAIT0()  asm volatile("cp.async.wait_group 0;" ::: "memory")

// ---------------- kernel 0: weight concat + fp16 split -----------------------
__global__ void prep_kernel(const float* __restrict__ Wq, const float* __restrict__ bq,
                            const float* __restrict__ Wk, const float* __restrict__ bk,
                            const float* __restrict__ Wv, const float* __restrict__ bv) {
    int i = blockIdx.x * blockDim.x + threadIdx.x;
    if (i < JTOT*CC) {
        int j = i / CC, k = i % CC;
        float v;
        if (j < 64)       v = Wq[j*CC + k];
        else if (j < 128) v = Wk[(j-64)*CC + k];
        else              v = Wv[(j-128)*CC + k];
        __half h = __float2half_rn(v);
        g_Whi[i] = h;
        g_Wlo[i] = __float2half_rn(v - __half2float(h));
    }
    if (i < JTOT) {
        g_bcat[i] = (i < 64) ? bq[i] : (i < 128) ? bk[i-64] : bv[i-128];
    }
}

// ---------------- kernel 1: QKV projection (fp16 warp MMA, fused passes) -----
// jt 0,1 (Q,K): 3 fused combos (Ah*Bh + Ah*Bl + Al*Bh). jt 2..5 (V): Ah*Bh only.
#define OFF_BH   0
#define OFF_BL   32768
#define OFF_A    65536       // 4 x 8KB: buf0 hi/lo, buf1 hi/lo
#define OFF_STG  65536       // epilogue overlay
#define OFF_BIAS 98304
#define QKV_SMEM 99840
#define STGP 66

__global__ __launch_bounds__(256) void qkv_mma_kernel(const float* __restrict__ x) {
    extern __shared__ __align__(128) char smq[];
    uint32_t sb = smem_u32(smq);
    int tid = threadIdx.x, wid = tid >> 5, lane = tid & 31;
    int pBase = blockIdx.x * 64;
    int bz = blockIdx.y;
    int warpM = wid & 1, warpN = wid >> 1;   // 2 x 4
    int jW = warpM * 32, pW = warpN * 16;

    for (int t = tid; t < JTOT; t += 256)
        *(float*)(smq + OFF_BIAS + t*4) = g_bcat[t];

    // A(jt0, ch0) -> buf0
    for (int t = tid; t < 512; t += 256) {
        int j = t >> 3, sg = t & 7;
        uint32_t sw = (uint32_t)(j*128 + ((sg ^ (j & 7))*16));
        CP_ASYNC16(sb + OFF_A + sw,        g_Whi + j*CC + sg*8);
        CP_ASYNC16(sb + OFF_A + 8192 + sw, g_Wlo + j*CC + sg*8);
    }
    CP_COMMIT();

    // B resident: fp32 x -> fp16 hi/lo, swizzled 128B rows
    {
        const float* xb = x + (size_t)bz*CC*PP;
        for (int t = tid; t < 4096; t += 256) {
            int k = t >> 4, sg = t & 15;
            float4 v = *(const float4*)&xb[(size_t)k*PP + pBase + sg*4];
            uint2 hi, lo; cvt_hilo_h(v, hi, lo);
            uint32_t sw = (uint32_t)(k*128 + (((sg>>1) ^ (k & 7))*16) + (sg&1)*8);
            *(uint2*)(smq + OFF_BH + sw) = hi;
            *(uint2*)(smq + OFF_BL + sw) = lo;
        }
    }

    int rA   = lane & 15;
    int swzA = rA & 7;
    int aseg = lane >> 4;
    int swzB = lane & 7;
    int bseg = (pW >> 3);

    for (int jt = 0; jt < 6; jt++) {
        float acc[2][2][4] = {};
        bool threepass = (jt < 2);

        for (int ch = 0; ch < 4; ch++) {
            CP_WAIT0();
            __syncthreads();
            if (ch < 3) {
                uint32_t dst = sb + OFF_A + (uint32_t)(((ch+1) & 1) * 16384);
                const __half* sH = g_Whi + (jt*64)*CC + (ch+1)*64;
                const __half* sL = g_Wlo + (jt*64)*CC + (ch+1)*64;
                for (int t = tid; t < 512; t += 256) {
                    int j = t >> 3, sg = t & 7;
                    uint32_t sw = (uint32_t)(j*128 + ((sg ^ (j & 7))*16));
                    CP_ASYNC16(dst + sw,        sH + j*CC + sg*8);
                    CP_ASYNC16(dst + 8192 + sw, sL + j*CC + sg*8);
                }
                CP_COMMIT();
            }
            uint32_t aBufH = sb + OFF_A + (uint32_t)((ch & 1) * 16384);
            uint32_t aBufL = aBufH + 8192;

            #pragma unroll
            for (int ksc = 0; ksc < 4; ksc++) {
                int ks16 = ch*4 + ksc;
                uint32_t ah[2][4], bhf[2][2];
                #pragma unroll
                for (int mi = 0; mi < 2; mi++) {
                    int row = jW + rA + mi*16;
                    ldsm_x4(ah[mi], aBufH + (uint32_t)(row*128 + (((ksc*2 + aseg) ^ swzA)*16)));
                }
                #pragma unroll
                for (int ni = 0; ni < 2; ni++) {
                    int row = ks16*16 + rA;
                    ldsm_x2t(bhf[ni], sb + OFF_BH + (uint32_t)(row*128 + (((bseg + ni) ^ swzB)*16)));
                }
                #pragma unroll
                for (int mi = 0; mi < 2; mi++)
                    #pragma unroll
                    for (int ni = 0; ni < 2; ni++)
                        mma_h(acc[mi][ni], ah[mi], bhf[ni]);
                if (threepass) {
                    uint32_t al[2][4], blf[2][2];
                    #pragma unroll
                    for (int mi = 0; mi < 2; mi++) {
                        int row = jW + rA + mi*16;
                        ldsm_x4(al[mi], aBufL + (uint32_t)(row*128 + (((ksc*2 + aseg) ^ swzA)*16)));
                    }
                    #pragma unroll
                    for (int ni = 0; ni < 2; ni++) {
                        int row = ks16*16 + rA;
                        ldsm_x2t(blf[ni], sb + OFF_BL + (uint32_t)(row*128 + (((bseg + ni) ^ swzB)*16)));
                    }
                    #pragma unroll
                    for (int mi = 0; mi < 2; mi++)
                        #pragma unroll
                        for (int ni = 0; ni < 2; ni++) {
                            mma_h(acc[mi][ni], ah[mi], blf[ni]);
                            mma_h(acc[mi][ni], al[mi], bhf[ni]);
                        }
                }
            }
        }
        __syncthreads();

        float* stg = (float*)(smq + OFF_STG);
        {
            int r = lane >> 2, c2 = (lane & 3) * 2;
            #pragma unroll
            for (int mi = 0; mi < 2; mi++)
                #pragma unroll
                for (int ni = 0; ni < 2; ni++) {
                    int j = jW + mi*16 + r;
                    int p = pW + ni*8 + c2;
                    stg[p*STGP + j]         = acc[mi][ni][0];
                    stg[(p+1)*STGP + j]     = acc[mi][ni][1];
                    stg[p*STGP + j + 8]     = acc[mi][ni][2];
                    stg[(p+1)*STGP + j + 8] = acc[mi][ni][3];
                }
        }
        __syncthreads();

        const float* sBias = (const float*)(smq + OFF_BIAS) + jt*64;
        for (int idx = tid; idx < 2048; idx += 256) {
            int pl = idx >> 5, j = (idx & 31) * 2;
            float v0 = stg[pl*STGP + j]     + sBias[j];
            float v1 = stg[pl*STGP + j + 1] + sBias[j + 1];
            __half h0 = __float2half_rn(v0), h1 = __float2half_rn(v1);
            __half2 hh = __halves2half2(h0, h1);
            int p = pBase + pl;
            int h = p / WW, w = p - h*WW;
            size_t col = (size_t)(bz*WW + w)*HH + h;
            if (jt == 0) {
                __half2 ll = __halves2half2(__float2half_rn(v0 - __half2float(h0)),
                                            __float2half_rn(v1 - __half2float(h1)));
                *(__half2*)(g_Qhi + col*QKD + j) = hh;
                *(__half2*)(g_Qlo + col*QKD + j) = ll;
            } else if (jt == 1) {
                __half2 ll = __halves2half2(__float2half_rn(v0 - __half2float(h0)),
                                            __float2half_rn(v1 - __half2float(h1)));
                *(__half2*)(g_Khi + col*QKD + j) = hh;
                *(__half2*)(g_Klo + col*QKD + j) = ll;
            } else {
                *(__half2*)(g_Vhi + col*CC + (jt-2)*64 + j) = hh;
            }
        }
        __syncthreads();

        if (jt < 5) {
            const __half* sH = g_Whi + ((jt+1)*64)*CC;
            const __half* sL = g_Wlo + ((jt+1)*64)*CC;
            for (int t = tid; t < 512; t += 256) {
                int j = t >> 3, sg = t & 7;
                uint32_t sw = (uint32_t)(j*128 + ((sg ^ (j & 7))*16));
                CP_ASYNC16(sb + OFF_A + sw,        sH + j*CC + sg*8);
                CP_ASYNC16(sb + OFF_A + 8192 + sw, sL + j*CC + sg*8);
            }
            CP_COMMIT();
        }
    }
}

// ---------------- kernel 2: per-(b,w) column attention ------------------------
// Register-resident scores, cross-warp softmax, resident V, direct O stores.
#define AOFF_QH 0
#define AOFF_QL 12288
#define AOFF_KH 24576
#define AOFF_KL 36864
#define AOFF_STAT 49152        // pmax[4][96] + psum[4][96] = 3072B (dead before V stage)
#define AOFF_A  0              // fp16 96 x 104 (pitch 208B) overlays Q
#define AOFF_V  24576          // 4 chunks x 12288 (overlays K + STAT)
#define ATT_SMEM 73728
#define APITCH 208

__global__ __launch_bounds__(256) void attn_mma_kernel() {
    extern __shared__ __align__(128) char sma[];
    uint32_t sb = smem_u32(sma);
    int tid = threadIdx.x, wid = tid >> 5, lane = tid & 31;
    int bw = blockIdx.x;
    int swz = lane & 7;

    // ---- stage Q,K (swizzled 128B rows)
    {
        const __half* Qh = g_Qhi + (size_t)bw*HH*QKD;
        const __half* Ql = g_Qlo + (size_t)bw*HH*QKD;
        const __half* Kh = g_Khi + (size_t)bw*HH*QKD;
        const __half* Kl = g_Klo + (size_t)bw*HH*QKD;
        for (int i = tid; i < 768; i += 256) {
            int h = i >> 3, sg = i & 7;
            uint32_t sw = (uint32_t)(h*128 + ((sg ^ (h & 7))*16));
            int go = h*QKD + sg*8;
            *(uint4*)(sma + AOFF_QH + sw) = *(const uint4*)(Qh + go);
            *(uint4*)(sma + AOFF_QL + sw) = *(const uint4*)(Ql + go);
            *(uint4*)(sma + AOFF_KH + sw) = *(const uint4*)(Kh + go);
            *(uint4*)(sma + AOFF_KL + sw) = *(const uint4*)(Kl + go);
        }
    }
    __syncthreads();

    int warpM = wid & 1, warpN = wid >> 1;
    int m0 = warpM * 48;
    int n0 = warpN * 24;
    int rq = lane >> 2, c2 = (lane & 3) * 2;

    // ---- scores: register-resident, warp tile 48m x 24n, 3 passes
    float acc[3][3][4] = {};
    #pragma unroll
    for (int pass = 0; pass < 3; pass++) {
        uint32_t aB = sb + ((pass == 2) ? AOFF_QL : AOFF_QH);
        uint32_t bB = sb + ((pass == 1) ? AOFF_KL : AOFF_KH);
        #pragma unroll
        for (int ks = 0; ks < 4; ks++) {
            uint32_t af[3][4], bf[3][2];
            #pragma unroll
            for (int mi = 0; mi < 3; mi++) {
                int row = m0 + (lane & 15) + mi*16;
                ldsm_x4(af[mi], aB + (uint32_t)(row*128 + (((ks*2 + (lane >> 4)) ^ swz)*16)));
            }
            #pragma unroll
            for (int nj = 0; nj < 3; nj++) {
                int row = n0 + nj*8 + (lane & 7);
                ldsm_x2(bf[nj], bB + (uint32_t)(row*128 + (((ks*2 + ((lane >> 3) & 1)) ^ swz)*16)));
            }
            #pragma unroll
            for (int mi = 0; mi < 3; mi++)
                #pragma unroll
                for (int nj = 0; nj < 3; nj++)
                    mma_h(acc[mi][nj], af[mi], bf[nj]);
        }
    }

    // ---- softmax: partial max -> cross-warp -> exp -> partial sum -> normalize
    float* pmax = (float*)(sma + AOFF_STAT);          // [4][96]
    float* psum = (float*)(sma + AOFF_STAT + 1536);   // [4][96]
    #pragma unroll
    for (int mi = 0; mi < 3; mi++) {
        float m0v = fmaxf(fmaxf(acc[mi][0][0], acc[mi][0][1]),
                          fmaxf(acc[mi][1][0], acc[mi][1][1]));
        m0v = fmaxf(m0v, fmaxf(acc[mi][2][0], acc[mi][2][1]));
        float m1v = fmaxf(fmaxf(acc[mi][0][2], acc[mi][0][3]),
                          fmaxf(acc[mi][1][2], acc[mi][1][3]));
        m1v = fmaxf(m1v, fmaxf(acc[mi][2][2], acc[mi][2][3]));
        m0v = fmaxf(m0v, __shfl_xor_sync(0xffffffffu, m0v, 1));
        m0v = fmaxf(m0v, __shfl_xor_sync(0xffffffffu, m0v, 2));
        m1v = fmaxf(m1v, __shfl_xor_sync(0xffffffffu, m1v, 1));
        m1v = fmaxf(m1v, __shfl_xor_sync(0xffffffffu, m1v, 2));
        if ((lane & 3) == 0) {
            pmax[warpN*96 + m0 + mi*16 + rq]     = m0v;
            pmax[warpN*96 + m0 + mi*16 + rq + 8] = m1v;
        }
    }
    __syncthreads();
    #pragma unroll
    for (int mi = 0; mi < 3; mi++) {
        #pragma unroll
        for (int hf = 0; hf < 2; hf++) {
            int row = m0 + mi*16 + rq + hf*8;
            float gm = fmaxf(fmaxf(pmax[row], pmax[96 + row]),
                             fmaxf(pmax[192 + row], pmax[288 + row]));
            float s = 0.f;
            #pragma unroll
            for (int nj = 0; nj < 3; nj++) {
                float e0 = __expf(acc[mi][nj][hf*2]     - gm);
                float e1 = __expf(acc[mi][nj][hf*2 + 1] - gm);
                acc[mi][nj][hf*2] = e0; acc[mi][nj][hf*2 + 1] = e1;
                s += e0 + e1;
            }
            s += __shfl_xor_sync(0xffffffffu, s, 1);
            s += __shfl_xor_sync(0xffffffffu, s, 2);
            if ((lane & 3) == 0) psum[warpN*96 + row] = s;
        }
    }
    __syncthreads();
    {
        __half* sA = (__half*)(sma + AOFF_A);
        #pragma unroll
        for (int mi = 0; mi < 3; mi++) {
            #pragma unroll
            for (int hf = 0; hf < 2; hf++) {
                int row = m0 + mi*16 + rq + hf*8;
                float tot = psum[row] + psum[96 + row] + psum[192 + row] + psum[288 + row];
                float inv = 1.0f / tot;
                #pragma unroll
                for (int nj = 0; nj < 3; nj++) {
                    __half2 a2 = __floats2half2_rn(acc[mi][nj][hf*2] * inv,
                                                   acc[mi][nj][hf*2 + 1] * inv);
                    *(__half2*)&sA[row*(APITCH/2) + n0 + nj*8 + c2] = a2;
                }
            }
        }
    }
    __syncthreads();

    // ---- stage ALL of V once (4 chunks of [96][64], overlays K + STAT)
    const __half* Vh = g_Vhi + (size_t)bw*HH*CC;
    __half* Og = g_Ot + (size_t)bw*HH*CC;
    #pragma unroll
    for (int ck = 0; ck < 4; ck++) {
        for (int i = tid; i < 768; i += 256) {
            int g = i >> 3, sg = i & 7;
            uint32_t sw = (uint32_t)(g*128 + ((sg ^ (g & 7))*16));
            *(uint4*)(sma + AOFF_V + ck*12288 + sw) =
                *(const uint4*)(Vh + (size_t)g*CC + ck*64 + sg*8);
        }
    }
    __syncthreads();

    // ---- AV: warp owns V chunk = warpN (64 cols), two 32-col halves.
    // A fragments shared across 4 B fragments; O written directly to global.
    int chunk = warpN;
    uint32_t vBase = sb + AOFF_V + (uint32_t)(chunk*12288);
    #pragma unroll
    for (int half = 0; half < 2; half++) {
        float vacc[3][4][4] = {};
        #pragma unroll
        for (int ks = 0; ks < 6; ks++) {
            uint32_t af[3][4], bf[4][2];
            #pragma unroll
            for (int mi = 0; mi < 3; mi++) {
                int row = m0 + (lane & 15) + mi*16;
                ldsm_x4(af[mi], sb + AOFF_A + (uint32_t)(row*APITCH + ks*32 + (lane >> 4)*16));
            }
            #pragma unroll
            for (int ni = 0; ni < 4; ni++) {
                int row = ks*16 + (lane & 15);
                ldsm_x2t(bf[ni], vBase + (uint32_t)(row*128 + (((half*4 + ni) ^ swz)*16)));
            }
            #pragma unroll
            for (int mi = 0; mi < 3; mi++)
                #pragma unroll
                for (int ni = 0; ni < 4; ni++)
                    mma_h(vacc[mi][ni], af[mi], bf[ni]);
        }
        #pragma unroll
        for (int mi = 0; mi < 3; mi++)
            #pragma unroll
            for (int ni = 0; ni < 4; ni++) {
                int row = m0 + mi*16 + rq;
                int col = chunk*64 + half*32 + ni*8 + c2;
                *(__half2*)&Og[(size_t)row*CC + col] =
                    __floats2half2_rn(vacc[mi][ni][0], vacc[mi][ni][1]);
                *(__half2*)&Og[(size_t)(row+8)*CC + col] =
                    __floats2half2_rn(vacc[mi][ni][2], vacc[mi][ni][3]);
            }
    }
}

// ---------------- kernel 3: transpose back + residual ------------------------
__global__ __launch_bounds__(256) void out_kernel(const float* __restrict__ x,
                                                  const float* __restrict__ gamma,
                                                  float* __restrict__ out) {
    __shared__ float tile[32][33];
    int c0 = blockIdx.x * 32;
    int w0 = blockIdx.y * 32;
    int bh = blockIdx.z;
    int b = bh / HH, h = bh % HH;
    int tx = threadIdx.x, ty = threadIdx.y;
    float gm = gamma[0];
    const __half* Ob = g_Ot + (size_t)b * WW * HH * CC;
    #pragma unroll
    for (int i = 0; i < 4; i++) {
        int wl = ty + i*8;
        tile[wl][tx] = __half2float(Ob[(size_t)((w0 + wl)*HH + h)*CC + c0 + tx]);
    }
    __syncthreads();
    size_t base = (size_t)b * CC * PP + (size_t)h * WW;
    #pragma unroll
    for (int i = 0; i < 4; i++) {
        int cl = ty + i*8;
        size_t idx = base + (size_t)(c0 + cl) * PP + w0 + tx;
        out[idx] = gm * tile[tx][cl] + x[idx];
    }
}

// ---------------- launcher ---------------------------------------------------
extern "C" void kernel_launch(void* const* d_in, const int* in_sizes, int n_in,
                              void* d_out, int out_size) {
    const float* x     = (const float*)d_in[0];
    const float* Wq    = (const float*)d_in[1];
    const float* bq    = (const float*)d_in[2];
    const float* Wk    = (const float*)d_in[3];
    const float* bk    = (const float*)d_in[4];
    const float* Wv    = (const float*)d_in[5];
    const float* bv    = (const float*)d_in[6];
    const float* gamma = (const float*)d_in[7];
    float* out = (float*)d_out;

    cudaFuncSetAttribute(qkv_mma_kernel, cudaFuncAttributeMaxDynamicSharedMemorySize, QKV_SMEM);
    cudaFuncSetAttribute(attn_mma_kernel, cudaFuncAttributeMaxDynamicSharedMemorySize, ATT_SMEM);

    prep_kernel<<<(JTOT*CC + 255)/256, 256>>>(Wq, bq, Wk, bk, Wv, bv);
    qkv_mma_kernel<<<dim3(PP/64, BB), 256, QKV_SMEM>>>(x);
    attn_mma_kernel<<<dim3(BB*WW), 256, ATT_SMEM>>>();
    out_kernel<<<dim3(CC/32, WW/32, BB*HH), dim3(32, 8)>>>(x, gamma, out);
}

// round 10
// speedup vs baseline: 1.1399x; 1.1399x over previous
#include <cuda_runtime.h>
#include <cuda_fp16.h>
#include <cstdint>

#define BB 16
#define CC 256
#define HH 96
#define WW 96
#define QKD 64
#define PP (HH*WW)          // 9216
#define JTOT 384

// ---------------- scratch (static device memory; no allocs allowed) ----------
__device__ float g_bcat[JTOT];
__device__ __half g_Whi[JTOT*CC];
__device__ __half g_Wlo[JTOT*CC];
__device__ __half g_Qhi[(size_t)BB*WW*HH*QKD];      // [b*w*h][q]
__device__ __half g_Qlo[(size_t)BB*WW*HH*QKD];
__device__ __half g_Khi[(size_t)BB*WW*HH*QKD];
__device__ __half g_Klo[(size_t)BB*WW*HH*QKD];
__device__ __half g_Vhi[(size_t)BB*WW*HH*CC];       // [b*w*g][c] single fp16
__device__ __half g_Ot[(size_t)BB*WW*HH*CC];        // [b][w][h][c]  fp16

// ---------------- PTX helpers (baseline, sm_103-safe) ------------------------
__device__ __forceinline__ uint32_t smem_u32(const void* p) {
    uint32_t a;
    asm("{ .reg .u64 t; cvta.to.shared.u64 t, %1; cvt.u32.u64 %0, t; }" : "=r"(a) : "l"(p));
    return a;
}
__device__ __forceinline__ void ldsm_x4(uint32_t* r, uint32_t addr) {
    asm volatile("ldmatrix.sync.aligned.m8n8.x4.shared.b16 {%0,%1,%2,%3}, [%4];"
        : "=r"(r[0]), "=r"(r[1]), "=r"(r[2]), "=r"(r[3]) : "r"(addr));
}
__device__ __forceinline__ void ldsm_x2(uint32_t* r, uint32_t addr) {
    asm volatile("ldmatrix.sync.aligned.m8n8.x2.shared.b16 {%0,%1}, [%2];"
        : "=r"(r[0]), "=r"(r[1]) : "r"(addr));
}
__device__ __forceinline__ void ldsm_x2t(uint32_t* r, uint32_t addr) {
    asm volatile("ldmatrix.sync.aligned.m8n8.x2.trans.shared.b16 {%0,%1}, [%2];"
        : "=r"(r[0]), "=r"(r[1]) : "r"(addr));
}
__device__ __forceinline__ void mma_h(float* d, const uint32_t* a, const uint32_t* b) {
    asm volatile("mma.sync.aligned.m16n8k16.row.col.f32.f16.f16.f32 "
        "{%0,%1,%2,%3}, {%4,%5,%6,%7}, {%8,%9}, {%0,%1,%2,%3};"
        : "+f"(d[0]), "+f"(d[1]), "+f"(d[2]), "+f"(d[3])
        : "r"(a[0]), "r"(a[1]), "r"(a[2]), "r"(a[3]), "r"(b[0]), "r"(b[1]));
}
__device__ __forceinline__ void cvt_hilo_h(float4 v, uint2& hi, uint2& lo) {
    __half2 h0 = __float22half2_rn(make_float2(v.x, v.y));
    __half2 h1 = __float22half2_rn(make_float2(v.z, v.w));
    float2 f0 = __half22float2(h0), f1 = __half22float2(h1);
    __half2 l0 = __float22half2_rn(make_float2(v.x - f0.x, v.y - f0.y));
    __half2 l1 = __float22half2_rn(make_float2(v.z - f1.x, v.w - f1.y));
    hi = make_uint2(*(uint32_t*)&h0, *(uint32_t*)&h1);
    lo = make_uint2(*(uint32_t*)&l0, *(uint32_t*)&l1);
}
#define CP_ASYNC16(dst, src) \
    asm volatile("cp.async.cg.shared.global [%0], [%1], 16;" :: "r"(dst), "l"(src))
#define CP_COMMIT() asm volatile("cp.async.commit_group;" ::: "memory")
#define CP_WAIT0()  asm volatile("cp.async.wait_group 0;" ::: "memory")

// ---------------- kernel 0: weight concat + fp16 split -----------------------
__global__ void prep_kernel(const float* __restrict__ Wq, const float* __restrict__ bq,
                            const float* __restrict__ Wk, const float* __restrict__ bk,
                            const float* __restrict__ Wv, const float* __restrict__ bv) {
    int i = blockIdx.x * blockDim.x + threadIdx.x;
    if (i < JTOT*CC) {
        int j = i / CC, k = i % CC;
        float v;
        if (j < 64)       v = Wq[j*CC + k];
        else if (j < 128) v = Wk[(j-64)*CC + k];
        else              v = Wv[(j-128)*CC + k];
        __half h = __float2half_rn(v);
        g_Whi[i] = h;
        g_Wlo[i] = __float2half_rn(v - __half2float(h));
    }
    if (i < JTOT) {
        g_bcat[i] = (i < 64) ? bq[i] : (i < 128) ? bk[i-64] : bv[i-128];
    }
}

// ---------------- kernel 1: QKV projection (fp16 warp MMA, fused passes) -----
// jt 0,1 (Q,K): 3 fused combos (Ah*Bh + Ah*Bl + Al*Bh). jt 2..5 (V): Ah*Bh only.
#define OFF_BH   0
#define OFF_BL   32768
#define OFF_A    65536       // 4 x 8KB: buf0 hi/lo, buf1 hi/lo
#define OFF_STG  65536       // epilogue overlay
#define OFF_BIAS 98304
#define QKV_SMEM 99840
#define STGP 66

__global__ __launch_bounds__(256) void qkv_mma_kernel(const float* __restrict__ x) {
    extern __shared__ __align__(128) char smq[];
    uint32_t sb = smem_u32(smq);
    int tid = threadIdx.x, wid = tid >> 5, lane = tid & 31;
    int pBase = blockIdx.x * 64;
    int bz = blockIdx.y;
    int warpM = wid & 1, warpN = wid >> 1;   // 2 x 4
    int jW = warpM * 32, pW = warpN * 16;

    for (int t = tid; t < JTOT; t += 256)
        *(float*)(smq + OFF_BIAS + t*4) = g_bcat[t];

    // A(jt0, ch0) -> buf0
    for (int t = tid; t < 512; t += 256) {
        int j = t >> 3, sg = t & 7;
        uint32_t sw = (uint32_t)(j*128 + ((sg ^ (j & 7))*16));
        CP_ASYNC16(sb + OFF_A + sw,        g_Whi + j*CC + sg*8);
        CP_ASYNC16(sb + OFF_A + 8192 + sw, g_Wlo + j*CC + sg*8);
    }
    CP_COMMIT();

    // B resident: fp32 x -> fp16 hi/lo, swizzled 128B rows
    {
        const float* xb = x + (size_t)bz*CC*PP;
        for (int t = tid; t < 4096; t += 256) {
            int k = t >> 4, sg = t & 15;
            float4 v = *(const float4*)&xb[(size_t)k*PP + pBase + sg*4];
            uint2 hi, lo; cvt_hilo_h(v, hi, lo);
            uint32_t sw = (uint32_t)(k*128 + (((sg>>1) ^ (k & 7))*16) + (sg&1)*8);
            *(uint2*)(smq + OFF_BH + sw) = hi;
            *(uint2*)(smq + OFF_BL + sw) = lo;
        }
    }

    int rA   = lane & 15;
    int swzA = rA & 7;
    int aseg = lane >> 4;
    int swzB = lane & 7;
    int bseg = (pW >> 3);

    for (int jt = 0; jt < 6; jt++) {
        float acc[2][2][4] = {};
        bool threepass = (jt < 2);

        for (int ch = 0; ch < 4; ch++) {
            CP_WAIT0();
            __syncthreads();
            if (ch < 3) {
                uint32_t dst = sb + OFF_A + (uint32_t)(((ch+1) & 1) * 16384);
                const __half* sH = g_Whi + (jt*64)*CC + (ch+1)*64;
                const __half* sL = g_Wlo + (jt*64)*CC + (ch+1)*64;
                for (int t = tid; t < 512; t += 256) {
                    int j = t >> 3, sg = t & 7;
                    uint32_t sw = (uint32_t)(j*128 + ((sg ^ (j & 7))*16));
                    CP_ASYNC16(dst + sw,        sH + j*CC + sg*8);
                    CP_ASYNC16(dst + 8192 + sw, sL + j*CC + sg*8);
                }
                CP_COMMIT();
            }
            uint32_t aBufH = sb + OFF_A + (uint32_t)((ch & 1) * 16384);
            uint32_t aBufL = aBufH + 8192;

            #pragma unroll
            for (int ksc = 0; ksc < 4; ksc++) {
                int ks16 = ch*4 + ksc;
                uint32_t ah[2][4], bhf[2][2];
                #pragma unroll
                for (int mi = 0; mi < 2; mi++) {
                    int row = jW + rA + mi*16;
                    ldsm_x4(ah[mi], aBufH + (uint32_t)(row*128 + (((ksc*2 + aseg) ^ swzA)*16)));
                }
                #pragma unroll
                for (int ni = 0; ni < 2; ni++) {
                    int row = ks16*16 + rA;
                    ldsm_x2t(bhf[ni], sb + OFF_BH + (uint32_t)(row*128 + (((bseg + ni) ^ swzB)*16)));
                }
                #pragma unroll
                for (int mi = 0; mi < 2; mi++)
                    #pragma unroll
                    for (int ni = 0; ni < 2; ni++)
                        mma_h(acc[mi][ni], ah[mi], bhf[ni]);
                if (threepass) {
                    uint32_t al[2][4], blf[2][2];
                    #pragma unroll
                    for (int mi = 0; mi < 2; mi++) {
                        int row = jW + rA + mi*16;
                        ldsm_x4(al[mi], aBufL + (uint32_t)(row*128 + (((ksc*2 + aseg) ^ swzA)*16)));
                    }
                    #pragma unroll
                    for (int ni = 0; ni < 2; ni++) {
                        int row = ks16*16 + rA;
                        ldsm_x2t(blf[ni], sb + OFF_BL + (uint32_t)(row*128 + (((bseg + ni) ^ swzB)*16)));
                    }
                    #pragma unroll
                    for (int mi = 0; mi < 2; mi++)
                        #pragma unroll
                        for (int ni = 0; ni < 2; ni++) {
                            mma_h(acc[mi][ni], ah[mi], blf[ni]);
                            mma_h(acc[mi][ni], al[mi], bhf[ni]);
                        }
                }
            }
        }
        __syncthreads();

        float* stg = (float*)(smq + OFF_STG);
        {
            int r = lane >> 2, c2 = (lane & 3) * 2;
            #pragma unroll
            for (int mi = 0; mi < 2; mi++)
                #pragma unroll
                for (int ni = 0; ni < 2; ni++) {
                    int j = jW + mi*16 + r;
                    int p = pW + ni*8 + c2;
                    stg[p*STGP + j]         = acc[mi][ni][0];
                    stg[(p+1)*STGP + j]     = acc[mi][ni][1];
                    stg[p*STGP + j + 8]     = acc[mi][ni][2];
                    stg[(p+1)*STGP + j + 8] = acc[mi][ni][3];
                }
        }
        __syncthreads();

        const float* sBias = (const float*)(smq + OFF_BIAS) + jt*64;
        for (int idx = tid; idx < 2048; idx += 256) {
            int pl = idx >> 5, j = (idx & 31) * 2;
            float v0 = stg[pl*STGP + j]     + sBias[j];
            float v1 = stg[pl*STGP + j + 1] + sBias[j + 1];
            __half h0 = __float2half_rn(v0), h1 = __float2half_rn(v1);
            __half2 hh = __halves2half2(h0, h1);
            int p = pBase + pl;
            int h = p / WW, w = p - h*WW;
            size_t col = (size_t)(bz*WW + w)*HH + h;
            if (jt == 0) {
                __half2 ll = __halves2half2(__float2half_rn(v0 - __half2float(h0)),
                                            __float2half_rn(v1 - __half2float(h1)));
                *(__half2*)(g_Qhi + col*QKD + j) = hh;
                *(__half2*)(g_Qlo + col*QKD + j) = ll;
            } else if (jt == 1) {
                __half2 ll = __halves2half2(__float2half_rn(v0 - __half2float(h0)),
                                            __float2half_rn(v1 - __half2float(h1)));
                *(__half2*)(g_Khi + col*QKD + j) = hh;
                *(__half2*)(g_Klo + col*QKD + j) = ll;
            } else {
                *(__half2*)(g_Vhi + col*CC + (jt-2)*64 + j) = hh;
            }
        }
        __syncthreads();

        if (jt < 5) {
            const __half* sH = g_Whi + ((jt+1)*64)*CC;
            const __half* sL = g_Wlo + ((jt+1)*64)*CC;
            for (int t = tid; t < 512; t += 256) {
                int j = t >> 3, sg = t & 7;
                uint32_t sw = (uint32_t)(j*128 + ((sg ^ (j & 7))*16));
                CP_ASYNC16(sb + OFF_A + sw,        sH + j*CC + sg*8);
                CP_ASYNC16(sb + OFF_A + 8192 + sw, sL + j*CC + sg*8);
            }
            CP_COMMIT();
        }
    }
}

// ---------------- kernel 2: per-(b,w) column attention (round-8 proven) ------
#define AOFF_QH 0
#define AOFF_QL 12288
#define AOFF_KH 24576
#define AOFF_KL 36864
#define AOFF_STAT 49152        // pmax[4][96] + psum[4][96] = 3072B
#define AOFF_A  0              // fp16 96 x 104 (pitch 208B) overlays Q
#define AOFF_VH 24576          // overlays KH
#define AOFF_O  36864          // fp16 96 x 72 = 13824
#define ATT_SMEM 52224
#define APITCH 208

__global__ __launch_bounds__(256) void attn_mma_kernel() {
    extern __shared__ __align__(128) char sma[];
    uint32_t sb = smem_u32(sma);
    int tid = threadIdx.x, wid = tid >> 5, lane = tid & 31;
    int bw = blockIdx.x;
    int swz = lane & 7;

    // ---- stage Q,K (swizzled 128B rows)
    {
        const __half* Qh = g_Qhi + (size_t)bw*HH*QKD;
        const __half* Ql = g_Qlo + (size_t)bw*HH*QKD;
        const __half* Kh = g_Khi + (size_t)bw*HH*QKD;
        const __half* Kl = g_Klo + (size_t)bw*HH*QKD;
        for (int i = tid; i < 768; i += 256) {
            int h = i >> 3, sg = i & 7;
            uint32_t sw = (uint32_t)(h*128 + ((sg ^ (h & 7))*16));
            int go = h*QKD + sg*8;
            *(uint4*)(sma + AOFF_QH + sw) = *(const uint4*)(Qh + go);
            *(uint4*)(sma + AOFF_QL + sw) = *(const uint4*)(Ql + go);
            *(uint4*)(sma + AOFF_KH + sw) = *(const uint4*)(Kh + go);
            *(uint4*)(sma + AOFF_KL + sw) = *(const uint4*)(Kl + go);
        }
    }
    __syncthreads();

    int warpM = wid & 1, warpN = wid >> 1;
    int m0 = warpM * 48;
    int n0 = warpN * 24;
    int rq = lane >> 2, c2 = (lane & 3) * 2;

    // ---- scores: register-resident, warp tile 48m x 24n, 3 passes
    float acc[3][3][4] = {};
    #pragma unroll
    for (int pass = 0; pass < 3; pass++) {
        uint32_t aB = sb + ((pass == 2) ? AOFF_QL : AOFF_QH);
        uint32_t bB = sb + ((pass == 1) ? AOFF_KL : AOFF_KH);
        #pragma unroll
        for (int ks = 0; ks < 4; ks++) {
            uint32_t af[3][4], bf[3][2];
            #pragma unroll
            for (int mi = 0; mi < 3; mi++) {
                int row = m0 + (lane & 15) + mi*16;
                ldsm_x4(af[mi], aB + (uint32_t)(row*128 + (((ks*2 + (lane >> 4)) ^ swz)*16)));
            }
            #pragma unroll
            for (int nj = 0; nj < 3; nj++) {
                int row = n0 + nj*8 + (lane & 7);
                ldsm_x2(bf[nj], bB + (uint32_t)(row*128 + (((ks*2 + ((lane >> 3) & 1)) ^ swz)*16)));
            }
            #pragma unroll
            for (int mi = 0; mi < 3; mi++)
                #pragma unroll
                for (int nj = 0; nj < 3; nj++)
                    mma_h(acc[mi][nj], af[mi], bf[nj]);
        }
    }

    // ---- softmax: partial max -> cross-warp -> exp -> partial sum -> normalize
    float* pmax = (float*)(sma + AOFF_STAT);          // [4][96]
    float* psum = (float*)(sma + AOFF_STAT + 1536);   // [4][96]
    #pragma unroll
    for (int mi = 0; mi < 3; mi++) {
        float m0v = fmaxf(fmaxf(acc[mi][0][0], acc[mi][0][1]),
                          fmaxf(acc[mi][1][0], acc[mi][1][1]));
        m0v = fmaxf(m0v, fmaxf(acc[mi][2][0], acc[mi][2][1]));
        float m1v = fmaxf(fmaxf(acc[mi][0][2], acc[mi][0][3]),
                          fmaxf(acc[mi][1][2], acc[mi][1][3]));
        m1v = fmaxf(m1v, fmaxf(acc[mi][2][2], acc[mi][2][3]));
        m0v = fmaxf(m0v, __shfl_xor_sync(0xffffffffu, m0v, 1));
        m0v = fmaxf(m0v, __shfl_xor_sync(0xffffffffu, m0v, 2));
        m1v = fmaxf(m1v, __shfl_xor_sync(0xffffffffu, m1v, 1));
        m1v = fmaxf(m1v, __shfl_xor_sync(0xffffffffu, m1v, 2));
        if ((lane & 3) == 0) {
            pmax[warpN*96 + m0 + mi*16 + rq]     = m0v;
            pmax[warpN*96 + m0 + mi*16 + rq + 8] = m1v;
        }
    }
    __syncthreads();
    #pragma unroll
    for (int mi = 0; mi < 3; mi++) {
        #pragma unroll
        for (int hf = 0; hf < 2; hf++) {
            int row = m0 + mi*16 + rq + hf*8;
            float gm = fmaxf(fmaxf(pmax[row], pmax[96 + row]),
                             fmaxf(pmax[192 + row], pmax[288 + row]));
            float s = 0.f;
            #pragma unroll
            for (int nj = 0; nj < 3; nj++) {
                float e0 = __expf(acc[mi][nj][hf*2]     - gm);
                float e1 = __expf(acc[mi][nj][hf*2 + 1] - gm);
                acc[mi][nj][hf*2] = e0; acc[mi][nj][hf*2 + 1] = e1;
                s += e0 + e1;
            }
            s += __shfl_xor_sync(0xffffffffu, s, 1);
            s += __shfl_xor_sync(0xffffffffu, s, 2);
            if ((lane & 3) == 0) psum[warpN*96 + row] = s;
        }
    }
    __syncthreads();
    {
        __half* sA = (__half*)(sma + AOFF_A);
        #pragma unroll
        for (int mi = 0; mi < 3; mi++) {
            #pragma unroll
            for (int hf = 0; hf < 2; hf++) {
                int row = m0 + mi*16 + rq + hf*8;
                float tot = psum[row] + psum[96 + row] + psum[192 + row] + psum[288 + row];
                float inv = 1.0f / tot;
                #pragma unroll
                for (int nj = 0; nj < 3; nj++) {
                    __half2 a2 = __floats2half2_rn(acc[mi][nj][hf*2] * inv,
                                                   acc[mi][nj][hf*2 + 1] * inv);
                    *(__half2*)&sA[row*(APITCH/2) + n0 + nj*8 + c2] = a2;
                }
            }
        }
    }
    __syncthreads();

    // ---- AV: O[h,c] = A·Vh; c chunks of 64, warp tile 48m x 16n
    const __half* Vh = g_Vhi + (size_t)bw*HH*CC;
    __half* Og = g_Ot + (size_t)bw*HH*CC;
    int cW = warpN * 16;
    int vseg = warpN * 2;

    for (int c0 = 0; c0 < CC; c0 += 64) {
        for (int i = tid; i < 768; i += 256) {
            int g = i >> 3, sg = i & 7;
            uint32_t sw = (uint32_t)(g*128 + ((sg ^ (g & 7))*16));
            *(uint4*)(sma + AOFF_VH + sw) = *(const uint4*)(Vh + (size_t)g*CC + c0 + sg*8);
        }
        __syncthreads();

        float vacc[3][2][4] = {};
        #pragma unroll
        for (int ks = 0; ks < 6; ks++) {
            uint32_t af[3][4], bh[2][2];
            #pragma unroll
            for (int mi = 0; mi < 3; mi++) {
                int row = m0 + (lane & 15) + mi*16;
                ldsm_x4(af[mi], sb + AOFF_A + (uint32_t)(row*APITCH + ks*32 + (lane >> 4)*16));
            }
            #pragma unroll
            for (int ni = 0; ni < 2; ni++) {
                int row = ks*16 + (lane & 15);
                ldsm_x2t(bh[ni], sb + AOFF_VH + (uint32_t)(row*128 + (((vseg + ni) ^ swz)*16)));
            }
            #pragma unroll
            for (int mi = 0; mi < 3; mi++)
                #pragma unroll
                for (int ni = 0; ni < 2; ni++)
                    mma_h(vacc[mi][ni], af[mi], bh[ni]);
        }
        __syncthreads();

        __half* sO = (__half*)(sma + AOFF_O);   // pitch 72 halfs
        #pragma unroll
        for (int mi = 0; mi < 3; mi++)
            #pragma unroll
            for (int ni = 0; ni < 2; ni++) {
                int row = m0 + mi*16 + rq, col = cW + ni*8 + c2;
                *(__half2*)&sO[row*72 + col]     = __floats2half2_rn(vacc[mi][ni][0], vacc[mi][ni][1]);
                *(__half2*)&sO[(row+8)*72 + col] = __floats2half2_rn(vacc[mi][ni][2], vacc[mi][ni][3]);
            }
        __syncthreads();

        for (int i = tid; i < 768; i += 256) {
            int h = i >> 3, c8 = (i & 7) * 8;
            *(uint4*)&Og[(size_t)h*CC + c0 + c8] = *(uint4*)&sO[h*72 + c8];
        }
        __syncthreads();
    }
}

// ---------------- kernel 3: transpose back + residual (coalesced Ot reads) ---
// tile 32w x 64c; Ot read via uint4 (8 halfs); fp32 smem pitch 66 (2-way max).
__global__ __launch_bounds__(256) void out_kernel(const float* __restrict__ x,
                                                  const float* __restrict__ gamma,
                                                  float* __restrict__ out) {
    __shared__ float tile[32][66];
    int c0 = blockIdx.x * 64;
    int w0 = blockIdx.y * 32;
    int bh = blockIdx.z;
    int b = bh / HH, h = bh % HH;
    int tid = threadIdx.x;
    float gm = gamma[0];
    const __half* Ob = g_Ot + (size_t)b * WW * HH * CC;
    {
        int wl = tid >> 3, cs = (tid & 7) * 8;
        uint4 v = *(const uint4*)(Ob + (size_t)((w0 + wl)*HH + h)*CC + c0 + cs);
        __half2* hp = (__half2*)&v;
        #pragma unroll
        for (int i = 0; i < 4; i++) {
            float2 f = __half22float2(hp[i]);
            *(float2*)&tile[wl][cs + i*2] = f;
        }
    }
    __syncthreads();
    {
        int cl = tid >> 2, ws = (tid & 3) * 8;
        size_t base = (size_t)b*CC*PP + (size_t)(c0 + cl)*PP + (size_t)h*WW + w0 + ws;
        float4 x0 = *(const float4*)&x[base];
        float4 x1 = *(const float4*)&x[base + 4];
        float4 o0, o1;
        o0.x = gm*tile[ws+0][cl] + x0.x;
        o0.y = gm*tile[ws+1][cl] + x0.y;
        o0.z = gm*tile[ws+2][cl] + x0.z;
        o0.w = gm*tile[ws+3][cl] + x0.w;
        o1.x = gm*tile[ws+4][cl] + x1.x;
        o1.y = gm*tile[ws+5][cl] + x1.y;
        o1.z = gm*tile[ws+6][cl] + x1.z;
        o1.w = gm*tile[ws+7][cl] + x1.w;
        *(float4*)&out[base]     = o0;
        *(float4*)&out[base + 4] = o1;
    }
}

// ---------------- launcher ---------------------------------------------------
extern "C" void kernel_launch(void* const* d_in, const int* in_sizes, int n_in,
                              void* d_out, int out_size) {
    const float* x     = (const float*)d_in[0];
    const float* Wq    = (const float*)d_in[1];
    const float* bq    = (const float*)d_in[2];
    const float* Wk    = (const float*)d_in[3];
    const float* bk    = (const float*)d_in[4];
    const float* Wv    = (const float*)d_in[5];
    const float* bv    = (const float*)d_in[6];
    const float* gamma = (const float*)d_in[7];
    float* out = (float*)d_out;

    cudaFuncSetAttribute(qkv_mma_kernel, cudaFuncAttributeMaxDynamicSharedMemorySize, QKV_SMEM);
    cudaFuncSetAttribute(attn_mma_kernel, cudaFuncAttributeMaxDynamicSharedMemorySize, ATT_SMEM);

    prep_kernel<<<(JTOT*CC + 255)/256, 256>>>(Wq, bq, Wk, bk, Wv, bv);
    qkv_mma_kernel<<<dim3(PP/64, BB), 256, QKV_SMEM>>>(x);
    attn_mma_kernel<<<dim3(BB*WW), 256, ATT_SMEM>>>();
    out_kernel<<<dim3(CC/64, WW/32, BB*HH), dim3(256)>>>(x, gamma, out);
}

// round 11
// speedup vs baseline: 1.2294x; 1.0785x over previous
#include <cuda_runtime.h>
#include <cuda_fp16.h>
#include <cstdint>

#define BB 16
#define CC 256
#define HH 96
#define WW 96
#define QKD 64
#define PP (HH*WW)          // 9216
#define JTOT 384

// ---------------- scratch (static device memory; no allocs allowed) ----------
__device__ float g_bcat[JTOT];
__device__ __half g_Whi[JTOT*CC];
__device__ __half g_Wlo[JTOT*CC];
__device__ __half g_Qhi[(size_t)BB*WW*HH*QKD];      // [b*w*h][q]
__device__ __half g_Qlo[(size_t)BB*WW*HH*QKD];
__device__ __half g_Khi[(size_t)BB*WW*HH*QKD];      // K single fp16
__device__ __half g_Vhi[(size_t)BB*WW*HH*CC];       // [b*w*g][c] single fp16
__device__ __half g_Ot[(size_t)BB*WW*HH*CC];        // [b][w][h][c]  fp16

// ---------------- PTX helpers (baseline, sm_103-safe) ------------------------
__device__ __forceinline__ uint32_t smem_u32(const void* p) {
    uint32_t a;
    asm("{ .reg .u64 t; cvta.to.shared.u64 t, %1; cvt.u32.u64 %0, t; }" : "=r"(a) : "l"(p));
    return a;
}
__device__ __forceinline__ void ldsm_x4(uint32_t* r, uint32_t addr) {
    asm volatile("ldmatrix.sync.aligned.m8n8.x4.shared.b16 {%0,%1,%2,%3}, [%4];"
        : "=r"(r[0]), "=r"(r[1]), "=r"(r[2]), "=r"(r[3]) : "r"(addr));
}
__device__ __forceinline__ void ldsm_x4t(uint32_t* r, uint32_t addr) {
    asm volatile("ldmatrix.sync.aligned.m8n8.x4.trans.shared.b16 {%0,%1,%2,%3}, [%4];"
        : "=r"(r[0]), "=r"(r[1]), "=r"(r[2]), "=r"(r[3]) : "r"(addr));
}
__device__ __forceinline__ void ldsm_x2(uint32_t* r, uint32_t addr) {
    asm volatile("ldmatrix.sync.aligned.m8n8.x2.shared.b16 {%0,%1}, [%2];"
        : "=r"(r[0]), "=r"(r[1]) : "r"(addr));
}
__device__ __forceinline__ void mma_h(float* d, const uint32_t* a, const uint32_t* b) {
    asm volatile("mma.sync.aligned.m16n8k16.row.col.f32.f16.f16.f32 "
        "{%0,%1,%2,%3}, {%4,%5,%6,%7}, {%8,%9}, {%0,%1,%2,%3};"
        : "+f"(d[0]), "+f"(d[1]), "+f"(d[2]), "+f"(d[3])
        : "r"(a[0]), "r"(a[1]), "r"(a[2]), "r"(a[3]), "r"(b[0]), "r"(b[1]));
}
__device__ __forceinline__ void cvt_hilo_h(float4 v, uint2& hi, uint2& lo) {
    __half2 h0 = __float22half2_rn(make_float2(v.x, v.y));
    __half2 h1 = __float22half2_rn(make_float2(v.z, v.w));
    float2 f0 = __half22float2(h0), f1 = __half22float2(h1);
    __half2 l0 = __float22half2_rn(make_float2(v.x - f0.x, v.y - f0.y));
    __half2 l1 = __float22half2_rn(make_float2(v.z - f1.x, v.w - f1.y));
    hi = make_uint2(*(uint32_t*)&h0, *(uint32_t*)&h1);
    lo = make_uint2(*(uint32_t*)&l0, *(uint32_t*)&l1);
}
#define CP_ASYNC16(dst, src) \
    asm volatile("cp.async.cg.shared.global [%0], [%1], 16;" :: "r"(dst), "l"(src))
#define CP_COMMIT() asm volatile("cp.async.commit_group;" ::: "memory")
#define CP_WAIT0()  asm volatile("cp.async.wait_group 0;" ::: "memory")

// ---------------- kernel 0: weight concat + fp16 split -----------------------
__global__ void prep_kernel(const float* __restrict__ Wq, const float* __restrict__ bq,
                            const float* __restrict__ Wk, const float* __restrict__ bk,
                            const float* __restrict__ Wv, const float* __restrict__ bv) {
    int i = blockIdx.x * blockDim.x + threadIdx.x;
    if (i < JTOT*CC) {
        int j = i / CC, k = i % CC;
        float v;
        if (j < 64)       v = Wq[j*CC + k];
        else if (j < 128) v = Wk[(j-64)*CC + k];
        else              v = Wv[(j-128)*CC + k];
        __half h = __float2half_rn(v);
        g_Whi[i] = h;
        g_Wlo[i] = __float2half_rn(v - __half2float(h));
    }
    if (i < JTOT) {
        g_bcat[i] = (i < 64) ? bq[i] : (i < 128) ? bk[i-64] : bv[i-128];
    }
}

// ---------------- kernel 1: QKV projection (fp16 warp MMA) -------------------
// jt0 (Q): 3 passes; jt1 (K): 2 passes (Ah*Bh + Ah*Bl); jt 2..5 (V): 1 pass.
// W_lo staged only for jt0. B fragments via ldmatrix.x4.trans.
#define OFF_BH   0
#define OFF_BL   32768
#define OFF_A    65536       // 4 x 8KB: buf0 hi/lo, buf1 hi/lo
#define OFF_STG  65536       // epilogue overlay
#define OFF_BIAS 98304
#define QKV_SMEM 99840
#define STGP 66

__global__ __launch_bounds__(256) void qkv_mma_kernel(const float* __restrict__ x) {
    extern __shared__ __align__(128) char smq[];
    uint32_t sb = smem_u32(smq);
    int tid = threadIdx.x, wid = tid >> 5, lane = tid & 31;
    int pBase = blockIdx.x * 64;
    int bz = blockIdx.y;
    int warpM = wid & 1, warpN = wid >> 1;   // 2 x 4
    int jW = warpM * 32, pW = warpN * 16;

    for (int t = tid; t < JTOT; t += 256)
        *(float*)(smq + OFF_BIAS + t*4) = g_bcat[t];

    // A(jt0, ch0) -> buf0 (hi+lo; jt0 needs lo)
    for (int t = tid; t < 512; t += 256) {
        int j = t >> 3, sg = t & 7;
        uint32_t sw = (uint32_t)(j*128 + ((sg ^ (j & 7))*16));
        CP_ASYNC16(sb + OFF_A + sw,        g_Whi + j*CC + sg*8);
        CP_ASYNC16(sb + OFF_A + 8192 + sw, g_Wlo + j*CC + sg*8);
    }
    CP_COMMIT();

    // B resident: fp32 x -> fp16 hi/lo, swizzled 128B rows
    {
        const float* xb = x + (size_t)bz*CC*PP;
        for (int t = tid; t < 4096; t += 256) {
            int k = t >> 4, sg = t & 15;
            float4 v = *(const float4*)&xb[(size_t)k*PP + pBase + sg*4];
            uint2 hi, lo; cvt_hilo_h(v, hi, lo);
            uint32_t sw = (uint32_t)(k*128 + (((sg>>1) ^ (k & 7))*16) + (sg&1)*8);
            *(uint2*)(smq + OFF_BH + sw) = hi;
            *(uint2*)(smq + OFF_BL + sw) = lo;
        }
    }

    int rA   = lane & 15;
    int swzA = rA & 7;
    int aseg = lane >> 4;
    int swzB = lane & 7;
    int bseg = (pW >> 3);     // warpN*2

    for (int jt = 0; jt < 6; jt++) {
        float acc[2][2][4] = {};
        int passes = (jt == 0) ? 3 : (jt == 1) ? 2 : 1;

        for (int ch = 0; ch < 4; ch++) {
            CP_WAIT0();
            __syncthreads();
            if (ch < 3) {
                uint32_t dst = sb + OFF_A + (uint32_t)(((ch+1) & 1) * 16384);
                const __half* sH = g_Whi + (jt*64)*CC + (ch+1)*64;
                const __half* sL = g_Wlo + (jt*64)*CC + (ch+1)*64;
                for (int t = tid; t < 512; t += 256) {
                    int j = t >> 3, sg = t & 7;
                    uint32_t sw = (uint32_t)(j*128 + ((sg ^ (j & 7))*16));
                    CP_ASYNC16(dst + sw, sH + j*CC + sg*8);
                    if (jt == 0) CP_ASYNC16(dst + 8192 + sw, sL + j*CC + sg*8);
                }
                CP_COMMIT();
            }
            uint32_t aBufH = sb + OFF_A + (uint32_t)((ch & 1) * 16384);
            uint32_t aBufL = aBufH + 8192;

            #pragma unroll
            for (int ksc = 0; ksc < 4; ksc++) {
                int ks16 = ch*4 + ksc;
                uint32_t brow = (uint32_t)((ks16*16 + rA)*128 + (((bseg + aseg) ^ swzB)*16));
                uint32_t ah[2][4], bh4[4];
                #pragma unroll
                for (int mi = 0; mi < 2; mi++) {
                    int row = jW + rA + mi*16;
                    ldsm_x4(ah[mi], aBufH + (uint32_t)(row*128 + (((ksc*2 + aseg) ^ swzA)*16)));
                }
                ldsm_x4t(bh4, sb + OFF_BH + brow);
                #pragma unroll
                for (int mi = 0; mi < 2; mi++) {
                    mma_h(acc[mi][0], ah[mi], &bh4[0]);
                    mma_h(acc[mi][1], ah[mi], &bh4[2]);
                }
                if (passes >= 2) {
                    uint32_t bl4[4];
                    ldsm_x4t(bl4, sb + OFF_BL + brow);
                    #pragma unroll
                    for (int mi = 0; mi < 2; mi++) {
                        mma_h(acc[mi][0], ah[mi], &bl4[0]);
                        mma_h(acc[mi][1], ah[mi], &bl4[2]);
                    }
                }
                if (passes == 3) {
                    uint32_t al[2][4];
                    #pragma unroll
                    for (int mi = 0; mi < 2; mi++) {
                        int row = jW + rA + mi*16;
                        ldsm_x4(al[mi], aBufL + (uint32_t)(row*128 + (((ksc*2 + aseg) ^ swzA)*16)));
                    }
                    #pragma unroll
                    for (int mi = 0; mi < 2; mi++) {
                        mma_h(acc[mi][0], al[mi], &bh4[0]);
                        mma_h(acc[mi][1], al[mi], &bh4[2]);
                    }
                }
            }
        }
        __syncthreads();

        float* stg = (float*)(smq + OFF_STG);
        {
            int r = lane >> 2, c2 = (lane & 3) * 2;
            #pragma unroll
            for (int mi = 0; mi < 2; mi++)
                #pragma unroll
                for (int ni = 0; ni < 2; ni++) {
                    int j = jW + mi*16 + r;
                    int p = pW + ni*8 + c2;
                    stg[p*STGP + j]         = acc[mi][ni][0];
                    stg[(p+1)*STGP + j]     = acc[mi][ni][1];
                    stg[p*STGP + j + 8]     = acc[mi][ni][2];
                    stg[(p+1)*STGP + j + 8] = acc[mi][ni][3];
                }
        }
        __syncthreads();

        const float* sBias = (const float*)(smq + OFF_BIAS) + jt*64;
        for (int idx = tid; idx < 2048; idx += 256) {
            int pl = idx >> 5, j = (idx & 31) * 2;
            float v0 = stg[pl*STGP + j]     + sBias[j];
            float v1 = stg[pl*STGP + j + 1] + sBias[j + 1];
            __half h0 = __float2half_rn(v0), h1 = __float2half_rn(v1);
            __half2 hh = __halves2half2(h0, h1);
            int p = pBase + pl;
            int h = p / WW, w = p - h*WW;
            size_t col = (size_t)(bz*WW + w)*HH + h;
            if (jt == 0) {
                __half2 ll = __halves2half2(__float2half_rn(v0 - __half2float(h0)),
                                            __float2half_rn(v1 - __half2float(h1)));
                *(__half2*)(g_Qhi + col*QKD + j) = hh;
                *(__half2*)(g_Qlo + col*QKD + j) = ll;
            } else if (jt == 1) {
                *(__half2*)(g_Khi + col*QKD + j) = hh;
            } else {
                *(__half2*)(g_Vhi + col*CC + (jt-2)*64 + j) = hh;
            }
        }
        __syncthreads();

        if (jt < 5) {
            const __half* sH = g_Whi + ((jt+1)*64)*CC;
            for (int t = tid; t < 512; t += 256) {
                int j = t >> 3, sg = t & 7;
                uint32_t sw = (uint32_t)(j*128 + ((sg ^ (j & 7))*16));
                CP_ASYNC16(sb + OFF_A + sw, sH + j*CC + sg*8);
            }
            CP_COMMIT();
        }
    }
}

// ---------------- kernel 2: per-(b,w) column attention ------------------------
// scores = (Qh + Ql)·Kh (2 passes); register-resident softmax; single-fp16 V.
#define AOFF_QH 0
#define AOFF_QL 12288
#define AOFF_KH 24576
#define AOFF_STAT 36864        // pmax[4][96] + psum[4][96] = 3072B
#define AOFF_A  0              // fp16 96 x 104 (pitch 208B) overlays Q
#define AOFF_VH 24576          // overlays KH
#define AOFF_O  36864          // fp16 96 x 72 = 13824 (overlays STAT)
#define ATT_SMEM 50688
#define APITCH 208

__global__ __launch_bounds__(256) void attn_mma_kernel() {
    extern __shared__ __align__(128) char sma[];
    uint32_t sb = smem_u32(sma);
    int tid = threadIdx.x, wid = tid >> 5, lane = tid & 31;
    int bw = blockIdx.x;
    int swz = lane & 7;

    // ---- stage Qh, Ql, Kh (swizzled 128B rows)
    {
        const __half* Qh = g_Qhi + (size_t)bw*HH*QKD;
        const __half* Ql = g_Qlo + (size_t)bw*HH*QKD;
        const __half* Kh = g_Khi + (size_t)bw*HH*QKD;
        for (int i = tid; i < 768; i += 256) {
            int h = i >> 3, sg = i & 7;
            uint32_t sw = (uint32_t)(h*128 + ((sg ^ (h & 7))*16));
            int go = h*QKD + sg*8;
            *(uint4*)(sma + AOFF_QH + sw) = *(const uint4*)(Qh + go);
            *(uint4*)(sma + AOFF_QL + sw) = *(const uint4*)(Ql + go);
            *(uint4*)(sma + AOFF_KH + sw) = *(const uint4*)(Kh + go);
        }
    }
    __syncthreads();

    int warpM = wid & 1, warpN = wid >> 1;
    int m0 = warpM * 48;
    int n0 = warpN * 24;
    int rq = lane >> 2, c2 = (lane & 3) * 2;

    // ---- scores: register-resident, warp tile 48m x 24n, 2 passes
    float acc[3][3][4] = {};
    #pragma unroll
    for (int pass = 0; pass < 2; pass++) {
        uint32_t aB = sb + (pass ? AOFF_QL : AOFF_QH);
        #pragma unroll
        for (int ks = 0; ks < 4; ks++) {
            uint32_t af[3][4], bf4[4], bf2[2];
            #pragma unroll
            for (int mi = 0; mi < 3; mi++) {
                int row = m0 + (lane & 15) + mi*16;
                ldsm_x4(af[mi], aB + (uint32_t)(row*128 + (((ks*2 + (lane >> 4)) ^ swz)*16)));
            }
            {
                int row = n0 + ((lane >> 4) << 3) + (lane & 7);
                int seg = (ks*2 + ((lane >> 3) & 1)) ^ swz;
                ldsm_x4(bf4, sb + AOFF_KH + (uint32_t)(row*128 + seg*16));
            }
            {
                int row = n0 + 16 + (lane & 7);
                int seg = (ks*2 + ((lane >> 3) & 1)) ^ swz;
                ldsm_x2(bf2, sb + AOFF_KH + (uint32_t)(row*128 + seg*16));
            }
            #pragma unroll
            for (int mi = 0; mi < 3; mi++) {
                mma_h(acc[mi][0], af[mi], &bf4[0]);
                mma_h(acc[mi][1], af[mi], &bf4[2]);
                mma_h(acc[mi][2], af[mi], bf2);
            }
        }
    }

    // ---- softmax: partial max -> cross-warp -> exp -> partial sum -> normalize
    float* pmax = (float*)(sma + AOFF_STAT);          // [4][96]
    float* psum = (float*)(sma + AOFF_STAT + 1536);   // [4][96]
    #pragma unroll
    for (int mi = 0; mi < 3; mi++) {
        float m0v = fmaxf(fmaxf(acc[mi][0][0], acc[mi][0][1]),
                          fmaxf(acc[mi][1][0], acc[mi][1][1]));
        m0v = fmaxf(m0v, fmaxf(acc[mi][2][0], acc[mi][2][1]));
        float m1v = fmaxf(fmaxf(acc[mi][0][2], acc[mi][0][3]),
                          fmaxf(acc[mi][1][2], acc[mi][1][3]));
        m1v = fmaxf(m1v, fmaxf(acc[mi][2][2], acc[mi][2][3]));
        m0v = fmaxf(m0v, __shfl_xor_sync(0xffffffffu, m0v, 1));
        m0v = fmaxf(m0v, __shfl_xor_sync(0xffffffffu, m0v, 2));
        m1v = fmaxf(m1v, __shfl_xor_sync(0xffffffffu, m1v, 1));
        m1v = fmaxf(m1v, __shfl_xor_sync(0xffffffffu, m1v, 2));
        if ((lane & 3) == 0) {
            pmax[warpN*96 + m0 + mi*16 + rq]     = m0v;
            pmax[warpN*96 + m0 + mi*16 + rq + 8] = m1v;
        }
    }
    __syncthreads();
    #pragma unroll
    for (int mi = 0; mi < 3; mi++) {
        #pragma unroll
        for (int hf = 0; hf < 2; hf++) {
            int row = m0 + mi*16 + rq + hf*8;
            float gm = fmaxf(fmaxf(pmax[row], pmax[96 + row]),
                             fmaxf(pmax[192 + row], pmax[288 + row]));
            float s = 0.f;
            #pragma unroll
            for (int nj = 0; nj < 3; nj++) {
                float e0 = __expf(acc[mi][nj][hf*2]     - gm);
                float e1 = __expf(acc[mi][nj][hf*2 + 1] - gm);
                acc[mi][nj][hf*2] = e0; acc[mi][nj][hf*2 + 1] = e1;
                s += e0 + e1;
            }
            s += __shfl_xor_sync(0xffffffffu, s, 1);
            s += __shfl_xor_sync(0xffffffffu, s, 2);
            if ((lane & 3) == 0) psum[warpN*96 + row] = s;
        }
    }
    __syncthreads();
    {
        __half* sA = (__half*)(sma + AOFF_A);
        #pragma unroll
        for (int mi = 0; mi < 3; mi++) {
            #pragma unroll
            for (int hf = 0; hf < 2; hf++) {
                int row = m0 + mi*16 + rq + hf*8;
                float tot = psum[row] + psum[96 + row] + psum[192 + row] + psum[288 + row];
                float inv = 1.0f / tot;
                #pragma unroll
                for (int nj = 0; nj < 3; nj++) {
                    __half2 a2 = __floats2half2_rn(acc[mi][nj][hf*2] * inv,
                                                   acc[mi][nj][hf*2 + 1] * inv);
                    *(__half2*)&sA[row*(APITCH/2) + n0 + nj*8 + c2] = a2;
                }
            }
        }
    }
    __syncthreads();

    // ---- AV: O[h,c] = A·Vh; c chunks of 64, warp tile 48m x 16n (x4t B loads)
    const __half* Vh = g_Vhi + (size_t)bw*HH*CC;
    __half* Og = g_Ot + (size_t)bw*HH*CC;
    int cW = warpN * 16;
    int vseg = warpN * 2;

    for (int c0 = 0; c0 < CC; c0 += 64) {
        for (int i = tid; i < 768; i += 256) {
            int g = i >> 3, sg = i & 7;
            uint32_t sw = (uint32_t)(g*128 + ((sg ^ (g & 7))*16));
            *(uint4*)(sma + AOFF_VH + sw) = *(const uint4*)(Vh + (size_t)g*CC + c0 + sg*8);
        }
        __syncthreads();

        float vacc[3][2][4] = {};
        #pragma unroll
        for (int ks = 0; ks < 6; ks++) {
            uint32_t af[3][4], bh4[4];
            #pragma unroll
            for (int mi = 0; mi < 3; mi++) {
                int row = m0 + (lane & 15) + mi*16;
                ldsm_x4(af[mi], sb + AOFF_A + (uint32_t)(row*APITCH + ks*32 + (lane >> 4)*16));
            }
            {
                int row = ks*16 + (lane & 15);
                int seg = (vseg + (lane >> 4)) ^ swz;
                ldsm_x4t(bh4, sb + AOFF_VH + (uint32_t)(row*128 + seg*16));
            }
            #pragma unroll
            for (int mi = 0; mi < 3; mi++) {
                mma_h(vacc[mi][0], af[mi], &bh4[0]);
                mma_h(vacc[mi][1], af[mi], &bh4[2]);
            }
        }
        __syncthreads();

        __half* sO = (__half*)(sma + AOFF_O);   // pitch 72 halfs
        #pragma unroll
        for (int mi = 0; mi < 3; mi++)
            #pragma unroll
            for (int ni = 0; ni < 2; ni++) {
                int row = m0 + mi*16 + rq, col = cW + ni*8 + c2;
                *(__half2*)&sO[row*72 + col]     = __floats2half2_rn(vacc[mi][ni][0], vacc[mi][ni][1]);
                *(__half2*)&sO[(row+8)*72 + col] = __floats2half2_rn(vacc[mi][ni][2], vacc[mi][ni][3]);
            }
        __syncthreads();

        for (int i = tid; i < 768; i += 256) {
            int h = i >> 3, c8 = (i & 7) * 8;
            *(uint4*)&Og[(size_t)h*CC + c0 + c8] = *(uint4*)&sO[h*72 + c8];
        }
        __syncthreads();
    }
}

// ---------------- kernel 3: transpose back + residual (coalesced Ot reads) ---
__global__ __launch_bounds__(256) void out_kernel(const float* __restrict__ x,
                                                  const float* __restrict__ gamma,
                                                  float* __restrict__ out) {
    __shared__ float tile[32][66];
    int c0 = blockIdx.x * 64;
    int w0 = blockIdx.y * 32;
    int bh = blockIdx.z;
    int b = bh / HH, h = bh % HH;
    int tid = threadIdx.x;
    float gm = gamma[0];
    const __half* Ob = g_Ot + (size_t)b * WW * HH * CC;
    {
        int wl = tid >> 3, cs = (tid & 7) * 8;
        uint4 v = *(const uint4*)(Ob + (size_t)((w0 + wl)*HH + h)*CC + c0 + cs);
        __half2* hp = (__half2*)&v;
        #pragma unroll
        for (int i = 0; i < 4; i++) {
            float2 f = __half22float2(hp[i]);
            *(float2*)&tile[wl][cs + i*2] = f;
        }
    }
    __syncthreads();
    {
        int cl = tid >> 2, ws = (tid & 3) * 8;
        size_t base = (size_t)b*CC*PP + (size_t)(c0 + cl)*PP + (size_t)h*WW + w0 + ws;
        float4 x0 = *(const float4*)&x[base];
        float4 x1 = *(const float4*)&x[base + 4];
        float4 o0, o1;
        o0.x = gm*tile[ws+0][cl] + x0.x;
        o0.y = gm*tile[ws+1][cl] + x0.y;
        o0.z = gm*tile[ws+2][cl] + x0.z;
        o0.w = gm*tile[ws+3][cl] + x0.w;
        o1.x = gm*tile[ws+4][cl] + x1.x;
        o1.y = gm*tile[ws+5][cl] + x1.y;
        o1.z = gm*tile[ws+6][cl] + x1.z;
        o1.w = gm*tile[ws+7][cl] + x1.w;
        *(float4*)&out[base]     = o0;
        *(float4*)&out[base + 4] = o1;
    }
}

// ---------------- launcher ---------------------------------------------------
extern "C" void kernel_launch(void* const* d_in, const int* in_sizes, int n_in,
                              void* d_out, int out_size) {
    const float* x     = (const float*)d_in[0];
    const float* Wq    = (const float*)d_in[1];
    const float* bq    = (const float*)d_in[2];
    const float* Wk    = (const float*)d_in[3];
    const float* bk    = (const float*)d_in[4];
    const float* Wv    = (const float*)d_in[5];
    const float* bv    = (const float*)d_in[6];
    const float* gamma = (const float*)d_in[7];
    float* out = (float*)d_out;

    cudaFuncSetAttribute(qkv_mma_kernel, cudaFuncAttributeMaxDynamicSharedMemorySize, QKV_SMEM);
    cudaFuncSetAttribute(attn_mma_kernel, cudaFuncAttributeMaxDynamicSharedMemorySize, ATT_SMEM);

    prep_kernel<<<(JTOT*CC + 255)/256, 256>>>(Wq, bq, Wk, bk, Wv, bv);
    qkv_mma_kernel<<<dim3(PP/64, BB), 256, QKV_SMEM>>>(x);
    attn_mma_kernel<<<dim3(BB*WW), 256, ATT_SMEM>>>();
    out_kernel<<<dim3(CC/64, WW/32, BB*HH), dim3(256)>>>(x, gamma, out);
}

// round 12
// speedup vs baseline: 1.3279x; 1.0801x over previous
#include <cuda_runtime.h>
#include <cuda_fp16.h>
#include <cstdint>

#define BB 16
#define CC 256
#define HH 96
#define WW 96
#define QKD 64
#define PP (HH*WW)          // 9216
#define JTOT 384

// ---------------- scratch (static device memory; no allocs allowed) ----------
__device__ float g_bcat[JTOT];
__device__ __half g_Whi[JTOT*CC];
__device__ __half g_Wlo[JTOT*CC];
__device__ __half g_Qhi[(size_t)BB*WW*HH*QKD];      // Q single fp16
__device__ __half g_Khi[(size_t)BB*WW*HH*QKD];      // K single fp16
__device__ __half g_Vhi[(size_t)BB*WW*HH*CC];       // V single fp16
__device__ __half g_Ot[(size_t)BB*WW*HH*CC];        // [b][w][h][c]  fp16

// ---------------- PTX helpers (baseline, sm_103-safe) ------------------------
__device__ __forceinline__ uint32_t smem_u32(const void* p) {
    uint32_t a;
    asm("{ .reg .u64 t; cvta.to.shared.u64 t, %1; cvt.u32.u64 %0, t; }" : "=r"(a) : "l"(p));
    return a;
}
__device__ __forceinline__ void ldsm_x4(uint32_t* r, uint32_t addr) {
    asm volatile("ldmatrix.sync.aligned.m8n8.x4.shared.b16 {%0,%1,%2,%3}, [%4];"
        : "=r"(r[0]), "=r"(r[1]), "=r"(r[2]), "=r"(r[3]) : "r"(addr));
}
__device__ __forceinline__ void ldsm_x4t(uint32_t* r, uint32_t addr) {
    asm volatile("ldmatrix.sync.aligned.m8n8.x4.trans.shared.b16 {%0,%1,%2,%3}, [%4];"
        : "=r"(r[0]), "=r"(r[1]), "=r"(r[2]), "=r"(r[3]) : "r"(addr));
}
__device__ __forceinline__ void ldsm_x2(uint32_t* r, uint32_t addr) {
    asm volatile("ldmatrix.sync.aligned.m8n8.x2.shared.b16 {%0,%1}, [%2];"
        : "=r"(r[0]), "=r"(r[1]) : "r"(addr));
}
__device__ __forceinline__ void mma_h(float* d, const uint32_t* a, const uint32_t* b) {
    asm volatile("mma.sync.aligned.m16n8k16.row.col.f32.f16.f16.f32 "
        "{%0,%1,%2,%3}, {%4,%5,%6,%7}, {%8,%9}, {%0,%1,%2,%3};"
        : "+f"(d[0]), "+f"(d[1]), "+f"(d[2]), "+f"(d[3])
        : "r"(a[0]), "r"(a[1]), "r"(a[2]), "r"(a[3]), "r"(b[0]), "r"(b[1]));
}
__device__ __forceinline__ void cvt_hilo_h(float4 v, uint2& hi, uint2& lo) {
    __half2 h0 = __float22half2_rn(make_float2(v.x, v.y));
    __half2 h1 = __float22half2_rn(make_float2(v.z, v.w));
    float2 f0 = __half22float2(h0), f1 = __half22float2(h1);
    __half2 l0 = __float22half2_rn(make_float2(v.x - f0.x, v.y - f0.y));
    __half2 l1 = __float22half2_rn(make_float2(v.z - f1.x, v.w - f1.y));
    hi = make_uint2(*(uint32_t*)&h0, *(uint32_t*)&h1);
    lo = make_uint2(*(uint32_t*)&l0, *(uint32_t*)&l1);
}
#define CP_ASYNC16(dst, src) \
    asm volatile("cp.async.cg.shared.global [%0], [%1], 16;" :: "r"(dst), "l"(src))
#define CP_COMMIT() asm volatile("cp.async.commit_group;" ::: "memory")
#define CP_WAIT0()  asm volatile("cp.async.wait_group 0;" ::: "memory")

// ---------------- kernel 0: weight concat + fp16 split -----------------------
__global__ void prep_kernel(const float* __restrict__ Wq, const float* __restrict__ bq,
                            const float* __restrict__ Wk, const float* __restrict__ bk,
                            const float* __restrict__ Wv, const float* __restrict__ bv) {
    int i = blockIdx.x * blockDim.x + threadIdx.x;
    if (i < JTOT*CC) {
        int j = i / CC, k = i % CC;
        float v;
        if (j < 64)       v = Wq[j*CC + k];
        else if (j < 128) v = Wk[(j-64)*CC + k];
        else              v = Wv[(j-128)*CC + k];
        __half h = __float2half_rn(v);
        g_Whi[i] = h;
        g_Wlo[i] = __float2half_rn(v - __half2float(h));   // kept (unused) for safety
    }
    if (i < JTOT) {
        g_bcat[i] = (i < 64) ? bq[i] : (i < 128) ? bk[i-64] : bv[i-128];
    }
}

// ---------------- kernel 1: QKV projection (fp16 warp MMA) -------------------
// jt0 (Q), jt1 (K): 2 passes (Ah*Bh + Ah*Bl). jt 2..5 (V): 1 pass.
// Only W_hi staged (A buffers 2 x 8KB double-buffered).
#define OFF_BH   0
#define OFF_BL   32768
#define OFF_A    65536       // 2 x 8KB: buf0 hi, buf1 hi
#define OFF_STG  65536       // epilogue overlay (16896B, spans both A bufs)
#define OFF_BIAS 82432
#define QKV_SMEM 83968
#define STGP 66

__global__ __launch_bounds__(256) void qkv_mma_kernel(const float* __restrict__ x) {
    extern __shared__ __align__(128) char smq[];
    uint32_t sb = smem_u32(smq);
    int tid = threadIdx.x, wid = tid >> 5, lane = tid & 31;
    int pBase = blockIdx.x * 64;
    int bz = blockIdx.y;
    int warpM = wid & 1, warpN = wid >> 1;   // 2 x 4
    int jW = warpM * 32, pW = warpN * 16;

    for (int t = tid; t < JTOT; t += 256)
        *(float*)(smq + OFF_BIAS + t*4) = g_bcat[t];

    // A(jt0, ch0) -> buf0 (hi only)
    for (int t = tid; t < 512; t += 256) {
        int j = t >> 3, sg = t & 7;
        uint32_t sw = (uint32_t)(j*128 + ((sg ^ (j & 7))*16));
        CP_ASYNC16(sb + OFF_A + sw, g_Whi + j*CC + sg*8);
    }
    CP_COMMIT();

    // B resident: fp32 x -> fp16 hi/lo, swizzled 128B rows
    {
        const float* xb = x + (size_t)bz*CC*PP;
        for (int t = tid; t < 4096; t += 256) {
            int k = t >> 4, sg = t & 15;
            float4 v = *(const float4*)&xb[(size_t)k*PP + pBase + sg*4];
            uint2 hi, lo; cvt_hilo_h(v, hi, lo);
            uint32_t sw = (uint32_t)(k*128 + (((sg>>1) ^ (k & 7))*16) + (sg&1)*8);
            *(uint2*)(smq + OFF_BH + sw) = hi;
            *(uint2*)(smq + OFF_BL + sw) = lo;
        }
    }

    int rA   = lane & 15;
    int swzA = rA & 7;
    int aseg = lane >> 4;
    int swzB = lane & 7;
    int bseg = (pW >> 3);     // warpN*2

    for (int jt = 0; jt < 6; jt++) {
        float acc[2][2][4] = {};
        bool twopass = (jt < 2);

        for (int ch = 0; ch < 4; ch++) {
            CP_WAIT0();
            __syncthreads();
            if (ch < 3) {
                uint32_t dst = sb + OFF_A + (uint32_t)(((ch+1) & 1) * 8192);
                const __half* sH = g_Whi + (jt*64)*CC + (ch+1)*64;
                for (int t = tid; t < 512; t += 256) {
                    int j = t >> 3, sg = t & 7;
                    uint32_t sw = (uint32_t)(j*128 + ((sg ^ (j & 7))*16));
                    CP_ASYNC16(dst + sw, sH + j*CC + sg*8);
                }
                CP_COMMIT();
            }
            uint32_t aBufH = sb + OFF_A + (uint32_t)((ch & 1) * 8192);

            #pragma unroll
            for (int ksc = 0; ksc < 4; ksc++) {
                int ks16 = ch*4 + ksc;
                uint32_t brow = (uint32_t)((ks16*16 + rA)*128 + (((bseg + aseg) ^ swzB)*16));
                uint32_t ah[2][4], bh4[4];
                #pragma unroll
                for (int mi = 0; mi < 2; mi++) {
                    int row = jW + rA + mi*16;
                    ldsm_x4(ah[mi], aBufH + (uint32_t)(row*128 + (((ksc*2 + aseg) ^ swzA)*16)));
                }
                ldsm_x4t(bh4, sb + OFF_BH + brow);
                #pragma unroll
                for (int mi = 0; mi < 2; mi++) {
                    mma_h(acc[mi][0], ah[mi], &bh4[0]);
                    mma_h(acc[mi][1], ah[mi], &bh4[2]);
                }
                if (twopass) {
                    uint32_t bl4[4];
                    ldsm_x4t(bl4, sb + OFF_BL + brow);
                    #pragma unroll
                    for (int mi = 0; mi < 2; mi++) {
                        mma_h(acc[mi][0], ah[mi], &bl4[0]);
                        mma_h(acc[mi][1], ah[mi], &bl4[2]);
                    }
                }
            }
        }
        __syncthreads();

        float* stg = (float*)(smq + OFF_STG);
        {
            int r = lane >> 2, c2 = (lane & 3) * 2;
            #pragma unroll
            for (int mi = 0; mi < 2; mi++)
                #pragma unroll
                for (int ni = 0; ni < 2; ni++) {
                    int j = jW + mi*16 + r;
                    int p = pW + ni*8 + c2;
                    stg[p*STGP + j]         = acc[mi][ni][0];
                    stg[(p+1)*STGP + j]     = acc[mi][ni][1];
                    stg[p*STGP + j + 8]     = acc[mi][ni][2];
                    stg[(p+1)*STGP + j + 8] = acc[mi][ni][3];
                }
        }
        __syncthreads();

        const float* sBias = (const float*)(smq + OFF_BIAS) + jt*64;
        for (int idx = tid; idx < 2048; idx += 256) {
            int pl = idx >> 5, j = (idx & 31) * 2;
            float v0 = stg[pl*STGP + j]     + sBias[j];
            float v1 = stg[pl*STGP + j + 1] + sBias[j + 1];
            __half2 hh = __halves2half2(__float2half_rn(v0), __float2half_rn(v1));
            int p = pBase + pl;
            int h = p / WW, w = p - h*WW;
            size_t col = (size_t)(bz*WW + w)*HH + h;
            if (jt == 0)      *(__half2*)(g_Qhi + col*QKD + j) = hh;
            else if (jt == 1) *(__half2*)(g_Khi + col*QKD + j) = hh;
            else              *(__half2*)(g_Vhi + col*CC + (jt-2)*64 + j) = hh;
        }
        __syncthreads();

        if (jt < 5) {
            const __half* sH = g_Whi + ((jt+1)*64)*CC;
            for (int t = tid; t < 512; t += 256) {
                int j = t >> 3, sg = t & 7;
                uint32_t sw = (uint32_t)(j*128 + ((sg ^ (j & 7))*16));
                CP_ASYNC16(sb + OFF_A + sw, sH + j*CC + sg*8);
            }
            CP_COMMIT();
        }
    }
}

// ---------------- kernel 2: per-(b,w) column attention ------------------------
// scores = Qh·Kh (1 pass); register-resident softmax; single-fp16 V.
#define AOFF_QH 0
#define AOFF_KH 12288
#define AOFF_STAT 24576        // pmax[4][96] + psum[4][96] = 3072B
#define AOFF_A  0              // fp16 96 x 104 (pitch 208B) = 19968, overlays Q + K head
#define AOFF_VH 20480          // 12288 (overlays K tail + STAT; staged after softmax)
#define AOFF_O  32768          // fp16 96 x 72 = 13824
#define ATT_SMEM 46592
#define APITCH 208

__global__ __launch_bounds__(256) void attn_mma_kernel() {
    extern __shared__ __align__(128) char sma[];
    uint32_t sb = smem_u32(sma);
    int tid = threadIdx.x, wid = tid >> 5, lane = tid & 31;
    int bw = blockIdx.x;
    int swz = lane & 7;

    // ---- stage Qh, Kh (swizzled 128B rows)
    {
        const __half* Qh = g_Qhi + (size_t)bw*HH*QKD;
        const __half* Kh = g_Khi + (size_t)bw*HH*QKD;
        for (int i = tid; i < 768; i += 256) {
            int h = i >> 3, sg = i & 7;
            uint32_t sw = (uint32_t)(h*128 + ((sg ^ (h & 7))*16));
            int go = h*QKD + sg*8;
            *(uint4*)(sma + AOFF_QH + sw) = *(const uint4*)(Qh + go);
            *(uint4*)(sma + AOFF_KH + sw) = *(const uint4*)(Kh + go);
        }
    }
    __syncthreads();

    int warpM = wid & 1, warpN = wid >> 1;
    int m0 = warpM * 48;
    int n0 = warpN * 24;
    int rq = lane >> 2, c2 = (lane & 3) * 2;

    // ---- scores: register-resident, warp tile 48m x 24n, 1 pass
    float acc[3][3][4] = {};
    #pragma unroll
    for (int ks = 0; ks < 4; ks++) {
        uint32_t af[3][4], bf4[4], bf2[2];
        #pragma unroll
        for (int mi = 0; mi < 3; mi++) {
            int row = m0 + (lane & 15) + mi*16;
            ldsm_x4(af[mi], sb + AOFF_QH + (uint32_t)(row*128 + (((ks*2 + (lane >> 4)) ^ swz)*16)));
        }
        {
            int row = n0 + ((lane >> 4) << 3) + (lane & 7);
            int seg = (ks*2 + ((lane >> 3) & 1)) ^ swz;
            ldsm_x4(bf4, sb + AOFF_KH + (uint32_t)(row*128 + seg*16));
        }
        {
            int row = n0 + 16 + (lane & 7);
            int seg = (ks*2 + ((lane >> 3) & 1)) ^ swz;
            ldsm_x2(bf2, sb + AOFF_KH + (uint32_t)(row*128 + seg*16));
        }
        #pragma unroll
        for (int mi = 0; mi < 3; mi++) {
            mma_h(acc[mi][0], af[mi], &bf4[0]);
            mma_h(acc[mi][1], af[mi], &bf4[2]);
            mma_h(acc[mi][2], af[mi], bf2);
        }
    }

    // ---- softmax: partial max -> cross-warp -> exp -> partial sum -> normalize
    float* pmax = (float*)(sma + AOFF_STAT);          // [4][96]
    float* psum = (float*)(sma + AOFF_STAT + 1536);   // [4][96]
    #pragma unroll
    for (int mi = 0; mi < 3; mi++) {
        float m0v = fmaxf(fmaxf(acc[mi][0][0], acc[mi][0][1]),
                          fmaxf(acc[mi][1][0], acc[mi][1][1]));
        m0v = fmaxf(m0v, fmaxf(acc[mi][2][0], acc[mi][2][1]));
        float m1v = fmaxf(fmaxf(acc[mi][0][2], acc[mi][0][3]),
                          fmaxf(acc[mi][1][2], acc[mi][1][3]));
        m1v = fmaxf(m1v, fmaxf(acc[mi][2][2], acc[mi][2][3]));
        m0v = fmaxf(m0v, __shfl_xor_sync(0xffffffffu, m0v, 1));
        m0v = fmaxf(m0v, __shfl_xor_sync(0xffffffffu, m0v, 2));
        m1v = fmaxf(m1v, __shfl_xor_sync(0xffffffffu, m1v, 1));
        m1v = fmaxf(m1v, __shfl_xor_sync(0xffffffffu, m1v, 2));
        if ((lane & 3) == 0) {
            pmax[warpN*96 + m0 + mi*16 + rq]     = m0v;
            pmax[warpN*96 + m0 + mi*16 + rq + 8] = m1v;
        }
    }
    __syncthreads();
    #pragma unroll
    for (int mi = 0; mi < 3; mi++) {
        #pragma unroll
        for (int hf = 0; hf < 2; hf++) {
            int row = m0 + mi*16 + rq + hf*8;
            float gm = fmaxf(fmaxf(pmax[row], pmax[96 + row]),
                             fmaxf(pmax[192 + row], pmax[288 + row]));
            float s = 0.f;
            #pragma unroll
            for (int nj = 0; nj < 3; nj++) {
                float e0 = __expf(acc[mi][nj][hf*2]     - gm);
                float e1 = __expf(acc[mi][nj][hf*2 + 1] - gm);
                acc[mi][nj][hf*2] = e0; acc[mi][nj][hf*2 + 1] = e1;
                s += e0 + e1;
            }
            s += __shfl_xor_sync(0xffffffffu, s, 1);
            s += __shfl_xor_sync(0xffffffffu, s, 2);
            if ((lane & 3) == 0) psum[warpN*96 + row] = s;
        }
    }
    __syncthreads();
    {
        __half* sA = (__half*)(sma + AOFF_A);
        #pragma unroll
        for (int mi = 0; mi < 3; mi++) {
            #pragma unroll
            for (int hf = 0; hf < 2; hf++) {
                int row = m0 + mi*16 + rq + hf*8;
                float tot = psum[row] + psum[96 + row] + psum[192 + row] + psum[288 + row];
                float inv = 1.0f / tot;
                #pragma unroll
                for (int nj = 0; nj < 3; nj++) {
                    __half2 a2 = __floats2half2_rn(acc[mi][nj][hf*2] * inv,
                                                   acc[mi][nj][hf*2 + 1] * inv);
                    *(__half2*)&sA[row*(APITCH/2) + n0 + nj*8 + c2] = a2;
                }
            }
        }
    }
    __syncthreads();

    // ---- AV: O[h,c] = A·Vh; c chunks of 64, warp tile 48m x 16n (x4t B loads)
    const __half* Vh = g_Vhi + (size_t)bw*HH*CC;
    __half* Og = g_Ot + (size_t)bw*HH*CC;
    int cW = warpN * 16;
    int vseg = warpN * 2;

    for (int c0 = 0; c0 < CC; c0 += 64) {
        for (int i = tid; i < 768; i += 256) {
            int g = i >> 3, sg = i & 7;
            uint32_t sw = (uint32_t)(g*128 + ((sg ^ (g & 7))*16));
            *(uint4*)(sma + AOFF_VH + sw) = *(const uint4*)(Vh + (size_t)g*CC + c0 + sg*8);
        }
        __syncthreads();

        float vacc[3][2][4] = {};
        #pragma unroll
        for (int ks = 0; ks < 6; ks++) {
            uint32_t af[3][4], bh4[4];
            #pragma unroll
            for (int mi = 0; mi < 3; mi++) {
                int row = m0 + (lane & 15) + mi*16;
                ldsm_x4(af[mi], sb + AOFF_A + (uint32_t)(row*APITCH + ks*32 + (lane >> 4)*16));
            }
            {
                int row = ks*16 + (lane & 15);
                int seg = (vseg + (lane >> 4)) ^ swz;
                ldsm_x4t(bh4, sb + AOFF_VH + (uint32_t)(row*128 + seg*16));
            }
            #pragma unroll
            for (int mi = 0; mi < 3; mi++) {
                mma_h(vacc[mi][0], af[mi], &bh4[0]);
                mma_h(vacc[mi][1], af[mi], &bh4[2]);
            }
        }
        __syncthreads();

        __half* sO = (__half*)(sma + AOFF_O);   // pitch 72 halfs
        #pragma unroll
        for (int mi = 0; mi < 3; mi++)
            #pragma unroll
            for (int ni = 0; ni < 2; ni++) {
                int row = m0 + mi*16 + rq, col = cW + ni*8 + c2;
                *(__half2*)&sO[row*72 + col]     = __floats2half2_rn(vacc[mi][ni][0], vacc[mi][ni][1]);
                *(__half2*)&sO[(row+8)*72 + col] = __floats2half2_rn(vacc[mi][ni][2], vacc[mi][ni][3]);
            }
        __syncthreads();

        for (int i = tid; i < 768; i += 256) {
            int h = i >> 3, c8 = (i & 7) * 8;
            *(uint4*)&Og[(size_t)h*CC + c0 + c8] = *(uint4*)&sO[h*72 + c8];
        }
        __syncthreads();
    }
}

// ---------------- kernel 3: transpose back + residual (coalesced Ot reads) ---
__global__ __launch_bounds__(256) void out_kernel(const float* __restrict__ x,
                                                  const float* __restrict__ gamma,
                                                  float* __restrict__ out) {
    __shared__ float tile[32][66];
    int c0 = blockIdx.x * 64;
    int w0 = blockIdx.y * 32;
    int bh = blockIdx.z;
    int b = bh / HH, h = bh % HH;
    int tid = threadIdx.x;
    float gm = gamma[0];
    const __half* Ob = g_Ot + (size_t)b * WW * HH * CC;
    {
        int wl = tid >> 3, cs = (tid & 7) * 8;
        uint4 v = *(const uint4*)(Ob + (size_t)((w0 + wl)*HH + h)*CC + c0 + cs);
        __half2* hp = (__half2*)&v;
        #pragma unroll
        for (int i = 0; i < 4; i++) {
            float2 f = __half22float2(hp[i]);
            *(float2*)&tile[wl][cs + i*2] = f;
        }
    }
    __syncthreads();
    {
        int cl = tid >> 2, ws = (tid & 3) * 8;
        size_t base = (size_t)b*CC*PP + (size_t)(c0 + cl)*PP + (size_t)h*WW + w0 + ws;
        float4 x0 = *(const float4*)&x[base];
        float4 x1 = *(const float4*)&x[base + 4];
        float4 o0, o1;
        o0.x = gm*tile[ws+0][cl] + x0.x;
        o0.y = gm*tile[ws+1][cl] + x0.y;
        o0.z = gm*tile[ws+2][cl] + x0.z;
        o0.w = gm*tile[ws+3][cl] + x0.w;
        o1.x = gm*tile[ws+4][cl] + x1.x;
        o1.y = gm*tile[ws+5][cl] + x1.y;
        o1.z = gm*tile[ws+6][cl] + x1.z;
        o1.w = gm*tile[ws+7][cl] + x1.w;
        *(float4*)&out[base]     = o0;
        *(float4*)&out[base + 4] = o1;
    }
}

// ---------------- launcher ---------------------------------------------------
extern "C" void kernel_launch(void* const* d_in, const int* in_sizes, int n_in,
                              void* d_out, int out_size) {
    const float* x     = (const float*)d_in[0];
    const float* Wq    = (const float*)d_in[1];
    const float* bq    = (const float*)d_in[2];
    const float* Wk    = (const float*)d_in[3];
    const float* bk    = (const float*)d_in[4];
    const float* Wv    = (const float*)d_in[5];
    const float* bv    = (const float*)d_in[6];
    const float* gamma = (const float*)d_in[7];
    float* out = (float*)d_out;

    cudaFuncSetAttribute(qkv_mma_kernel, cudaFuncAttributeMaxDynamicSharedMemorySize, QKV_SMEM);
    cudaFuncSetAttribute(attn_mma_kernel, cudaFuncAttributeMaxDynamicSharedMemorySize, ATT_SMEM);

    prep_kernel<<<(JTOT*CC + 255)/256, 256>>>(Wq, bq, Wk, bk, Wv, bv);
    qkv_mma_kernel<<<dim3(PP/64, BB), 256, QKV_SMEM>>>(x);
    attn_mma_kernel<<<dim3(BB*WW), 256, ATT_SMEM>>>();
    out_kernel<<<dim3(CC/64, WW/32, BB*HH), dim3(256)>>>(x, gamma, out);
}

// round 13
// speedup vs baseline: 1.6079x; 1.2108x over previous
#include <cuda_runtime.h>
#include <cuda_fp16.h>
#include <cstdint>

#define BB 16
#define CC 256
#define HH 96
#define WW 96
#define QKD 64
#define PP (HH*WW)          // 9216
#define JTOT 384

// ---------------- scratch (static device memory; no allocs allowed) ----------
__device__ float g_bcat[JTOT];
__device__ __half g_Whi[JTOT*CC];
__device__ __half g_Qhi[(size_t)BB*WW*HH*QKD];      // Q single fp16
__device__ __half g_Khi[(size_t)BB*WW*HH*QKD];      // K single fp16
__device__ __half g_Vhi[(size_t)BB*WW*HH*CC];       // V single fp16
__device__ __half g_Ot[(size_t)BB*WW*HH*CC];        // [b][w][h][c]  fp16

// ---------------- PTX helpers (baseline, sm_103-safe) ------------------------
__device__ __forceinline__ uint32_t smem_u32(const void* p) {
    uint32_t a;
    asm("{ .reg .u64 t; cvta.to.shared.u64 t, %1; cvt.u32.u64 %0, t; }" : "=r"(a) : "l"(p));
    return a;
}
__device__ __forceinline__ void ldsm_x4(uint32_t* r, uint32_t addr) {
    asm volatile("ldmatrix.sync.aligned.m8n8.x4.shared.b16 {%0,%1,%2,%3}, [%4];"
        : "=r"(r[0]), "=r"(r[1]), "=r"(r[2]), "=r"(r[3]) : "r"(addr));
}
__device__ __forceinline__ void ldsm_x4t(uint32_t* r, uint32_t addr) {
    asm volatile("ldmatrix.sync.aligned.m8n8.x4.trans.shared.b16 {%0,%1,%2,%3}, [%4];"
        : "=r"(r[0]), "=r"(r[1]), "=r"(r[2]), "=r"(r[3]) : "r"(addr));
}
__device__ __forceinline__ void ldsm_x2(uint32_t* r, uint32_t addr) {
    asm volatile("ldmatrix.sync.aligned.m8n8.x2.shared.b16 {%0,%1}, [%2];"
        : "=r"(r[0]), "=r"(r[1]) : "r"(addr));
}
__device__ __forceinline__ void mma_h(float* d, const uint32_t* a, const uint32_t* b) {
    asm volatile("mma.sync.aligned.m16n8k16.row.col.f32.f16.f16.f32 "
        "{%0,%1,%2,%3}, {%4,%5,%6,%7}, {%8,%9}, {%0,%1,%2,%3};"
        : "+f"(d[0]), "+f"(d[1]), "+f"(d[2]), "+f"(d[3])
        : "r"(a[0]), "r"(a[1]), "r"(a[2]), "r"(a[3]), "r"(b[0]), "r"(b[1]));
}
#define CP_ASYNC16(dst, src) \
    asm volatile("cp.async.cg.shared.global [%0], [%1], 16;" :: "r"(dst), "l"(src))
#define CP_COMMIT() asm volatile("cp.async.commit_group;" ::: "memory")
#define CP_WAIT0()  asm volatile("cp.async.wait_group 0;" ::: "memory")

// ---------------- kernel 0: weight concat (fp16 hi only) ---------------------
__global__ void prep_kernel(const float* __restrict__ Wq, const float* __restrict__ bq,
                            const float* __restrict__ Wk, const float* __restrict__ bk,
                            const float* __restrict__ Wv, const float* __restrict__ bv) {
    int i = blockIdx.x * blockDim.x + threadIdx.x;
    if (i < JTOT*CC) {
        int j = i / CC, k = i % CC;
        float v;
        if (j < 64)       v = Wq[j*CC + k];
        else if (j < 128) v = Wk[(j-64)*CC + k];
        else              v = Wv[(j-128)*CC + k];
        g_Whi[i] = __float2half_rn(v);
    }
    if (i < JTOT) {
        g_bcat[i] = (i < 64) ? bq[i] : (i < 128) ? bk[i-64] : bv[i-128];
    }
}

// ---------------- kernel 1: QKV projection (fp16 warp MMA, 1-pass uniform) ---
// All tiles W_hi * x_hi. B_hi resident; A double-buffered across ALL 24 chunks.
#define OFF_BH   0          // 32768
#define OFF_A    32768      // 2 x 8192
#define OFF_STG  49152      // 16896 (dedicated)
#define OFF_BIAS 66048      // 1536
#define QKV_SMEM 67584
#define STGP 66

__global__ __launch_bounds__(256, 3) void qkv_mma_kernel(const float* __restrict__ x) {
    extern __shared__ __align__(128) char smq[];
    uint32_t sb = smem_u32(smq);
    int tid = threadIdx.x, wid = tid >> 5, lane = tid & 31;
    int pBase = blockIdx.x * 64;
    int bz = blockIdx.y;
    int warpM = wid & 1, warpN = wid >> 1;   // 2 x 4
    int jW = warpM * 32, pW = warpN * 16;

    for (int t = tid; t < JTOT; t += 256)
        *(float*)(smq + OFF_BIAS + t*4) = g_bcat[t];

    // A chunk 0 -> buf0
    for (int t = tid; t < 512; t += 256) {
        int j = t >> 3, sg = t & 7;
        uint32_t sw = (uint32_t)(j*128 + ((sg ^ (j & 7))*16));
        CP_ASYNC16(sb + OFF_A + sw, g_Whi + j*CC + sg*8);
    }
    CP_COMMIT();

    // B resident: fp32 x -> fp16 hi, swizzled 128B rows
    {
        const float* xb = x + (size_t)bz*CC*PP;
        for (int t = tid; t < 4096; t += 256) {
            int k = t >> 4, sg = t & 15;
            float4 v = *(const float4*)&xb[(size_t)k*PP + pBase + sg*4];
            __half2 h0 = __float22half2_rn(make_float2(v.x, v.y));
            __half2 h1 = __float22half2_rn(make_float2(v.z, v.w));
            uint32_t sw = (uint32_t)(k*128 + (((sg>>1) ^ (k & 7))*16) + (sg&1)*8);
            *(uint2*)(smq + OFF_BH + sw) = make_uint2(*(uint32_t*)&h0, *(uint32_t*)&h1);
        }
    }

    int rA   = lane & 15;
    int swzA = rA & 7;
    int aseg = lane >> 4;
    int swzB = lane & 7;
    int bseg = (pW >> 3);     // warpN*2

    for (int jt = 0; jt < 6; jt++) {
        float acc[2][2][4] = {};

        for (int ch = 0; ch < 4; ch++) {
            CP_WAIT0();
            __syncthreads();
            // prefetch next A chunk (continuous pipeline across jt boundaries)
            int nit = jt*4 + ch + 1;
            if (nit < 24) {
                int njt = nit >> 2, nch = nit & 3;
                uint32_t dst = sb + OFF_A + (uint32_t)((nit & 1) * 8192);
                const __half* sH = g_Whi + (njt*64)*CC + nch*64;
                for (int t = tid; t < 512; t += 256) {
                    int j = t >> 3, sg = t & 7;
                    uint32_t sw = (uint32_t)(j*128 + ((sg ^ (j & 7))*16));
                    CP_ASYNC16(dst + sw, sH + j*CC + sg*8);
                }
                CP_COMMIT();
            }
            uint32_t aBufH = sb + OFF_A + (uint32_t)(((jt*4 + ch) & 1) * 8192);

            #pragma unroll
            for (int ksc = 0; ksc < 4; ksc++) {
                int ks16 = ch*4 + ksc;
                uint32_t brow = (uint32_t)((ks16*16 + rA)*128 + (((bseg + aseg) ^ swzB)*16));
                uint32_t ah[2][4], bh4[4];
                #pragma unroll
                for (int mi = 0; mi < 2; mi++) {
                    int row = jW + rA + mi*16;
                    ldsm_x4(ah[mi], aBufH + (uint32_t)(row*128 + (((ksc*2 + aseg) ^ swzA)*16)));
                }
                ldsm_x4t(bh4, sb + OFF_BH + brow);
                #pragma unroll
                for (int mi = 0; mi < 2; mi++) {
                    mma_h(acc[mi][0], ah[mi], &bh4[0]);
                    mma_h(acc[mi][1], ah[mi], &bh4[2]);
                }
            }
        }

        // ---- epilogue (stg is dedicated; previous jt's readers done at its end-sync)
        float* stg = (float*)(smq + OFF_STG);
        {
            int r = lane >> 2, c2 = (lane & 3) * 2;
            #pragma unroll
            for (int mi = 0; mi < 2; mi++)
                #pragma unroll
                for (int ni = 0; ni < 2; ni++) {
                    int j = jW + mi*16 + r;
                    int p = pW + ni*8 + c2;
                    stg[p*STGP + j]         = acc[mi][ni][0];
                    stg[(p+1)*STGP + j]     = acc[mi][ni][1];
                    stg[p*STGP + j + 8]     = acc[mi][ni][2];
                    stg[(p+1)*STGP + j + 8] = acc[mi][ni][3];
                }
        }
        __syncthreads();

        const float* sBias = (const float*)(smq + OFF_BIAS) + jt*64;
        for (int idx = tid; idx < 2048; idx += 256) {
            int pl = idx >> 5, j = (idx & 31) * 2;
            float v0 = stg[pl*STGP + j]     + sBias[j];
            float v1 = stg[pl*STGP + j + 1] + sBias[j + 1];
            __half2 hh = __halves2half2(__float2half_rn(v0), __float2half_rn(v1));
            int p = pBase + pl;
            int h = p / WW, w = p - h*WW;
            size_t col = (size_t)(bz*WW + w)*HH + h;
            if (jt == 0)      *(__half2*)(g_Qhi + col*QKD + j) = hh;
            else if (jt == 1) *(__half2*)(g_Khi + col*QKD + j) = hh;
            else              *(__half2*)(g_Vhi + col*CC + (jt-2)*64 + j) = hh;
        }
        __syncthreads();
    }
}

// ---------------- kernel 2: per-(b,w) column attention ------------------------
// V prefetched via cp.async at entry (overlaps scores+softmax); fully resident.
#define AOFF_Q   0          // 12288
#define AOFF_K   12288      // 12288
#define AOFF_A   0          // fp16 96x104 (19968) overlays Q + dead K head
#define AOFF_V   24576      // 4 chunks x 12288 = 49152
#define AOFF_O   73728      // fp16 96x72 = 13824
#define AOFF_STAT 87552     // 3072
#define ATT_SMEM 90624
#define APITCH 208

__global__ __launch_bounds__(256) void attn_mma_kernel() {
    extern __shared__ __align__(128) char sma[];
    uint32_t sb = smem_u32(sma);
    int tid = threadIdx.x, wid = tid >> 5, lane = tid & 31;
    int bw = blockIdx.x;
    int swz = lane & 7;

    // ---- prefetch ALL of V via cp.async (completes during scores/softmax)
    {
        const __half* Vh = g_Vhi + (size_t)bw*HH*CC;
        for (int t = tid; t < 3072; t += 256) {
            int g = t >> 5, cseg = t & 31;          // 32 x 16B per g-row (256 c)
            int ck = cseg >> 3, sg = cseg & 7;
            uint32_t dst = sb + AOFF_V + (uint32_t)(ck*12288 + g*128 + ((sg ^ (g & 7))*16));
            CP_ASYNC16(dst, Vh + (size_t)g*CC + cseg*8);
        }
        CP_COMMIT();
    }

    // ---- stage Qh, Kh (swizzled 128B rows)
    {
        const __half* Qh = g_Qhi + (size_t)bw*HH*QKD;
        const __half* Kh = g_Khi + (size_t)bw*HH*QKD;
        for (int i = tid; i < 768; i += 256) {
            int h = i >> 3, sg = i & 7;
            uint32_t sw = (uint32_t)(h*128 + ((sg ^ (h & 7))*16));
            int go = h*QKD + sg*8;
            *(uint4*)(sma + AOFF_Q + sw) = *(const uint4*)(Qh + go);
            *(uint4*)(sma + AOFF_K + sw) = *(const uint4*)(Kh + go);
        }
    }
    __syncthreads();

    int warpM = wid & 1, warpN = wid >> 1;
    int m0 = warpM * 48;
    int n0 = warpN * 24;
    int rq = lane >> 2, c2 = (lane & 3) * 2;

    // ---- scores: register-resident, warp tile 48m x 24n, 1 pass
    float acc[3][3][4] = {};
    #pragma unroll
    for (int ks = 0; ks < 4; ks++) {
        uint32_t af[3][4], bf4[4], bf2[2];
        #pragma unroll
        for (int mi = 0; mi < 3; mi++) {
            int row = m0 + (lane & 15) + mi*16;
            ldsm_x4(af[mi], sb + AOFF_Q + (uint32_t)(row*128 + (((ks*2 + (lane >> 4)) ^ swz)*16)));
        }
        {
            int row = n0 + ((lane >> 4) << 3) + (lane & 7);
            int seg = (ks*2 + ((lane >> 3) & 1)) ^ swz;
            ldsm_x4(bf4, sb + AOFF_K + (uint32_t)(row*128 + seg*16));
        }
        {
            int row = n0 + 16 + (lane & 7);
            int seg = (ks*2 + ((lane >> 3) & 1)) ^ swz;
            ldsm_x2(bf2, sb + AOFF_K + (uint32_t)(row*128 + seg*16));
        }
        #pragma unroll
        for (int mi = 0; mi < 3; mi++) {
            mma_h(acc[mi][0], af[mi], &bf4[0]);
            mma_h(acc[mi][1], af[mi], &bf4[2]);
            mma_h(acc[mi][2], af[mi], bf2);
        }
    }

    // ---- softmax: partial max -> cross-warp -> exp -> partial sum -> normalize
    float* pmax = (float*)(sma + AOFF_STAT);          // [4][96]
    float* psum = (float*)(sma + AOFF_STAT + 1536);   // [4][96]
    #pragma unroll
    for (int mi = 0; mi < 3; mi++) {
        float m0v = fmaxf(fmaxf(acc[mi][0][0], acc[mi][0][1]),
                          fmaxf(acc[mi][1][0], acc[mi][1][1]));
        m0v = fmaxf(m0v, fmaxf(acc[mi][2][0], acc[mi][2][1]));
        float m1v = fmaxf(fmaxf(acc[mi][0][2], acc[mi][0][3]),
                          fmaxf(acc[mi][1][2], acc[mi][1][3]));
        m1v = fmaxf(m1v, fmaxf(acc[mi][2][2], acc[mi][2][3]));
        m0v = fmaxf(m0v, __shfl_xor_sync(0xffffffffu, m0v, 1));
        m0v = fmaxf(m0v, __shfl_xor_sync(0xffffffffu, m0v, 2));
        m1v = fmaxf(m1v, __shfl_xor_sync(0xffffffffu, m1v, 1));
        m1v = fmaxf(m1v, __shfl_xor_sync(0xffffffffu, m1v, 2));
        if ((lane & 3) == 0) {
            pmax[warpN*96 + m0 + mi*16 + rq]     = m0v;
            pmax[warpN*96 + m0 + mi*16 + rq + 8] = m1v;
        }
    }
    __syncthreads();
    #pragma unroll
    for (int mi = 0; mi < 3; mi++) {
        #pragma unroll
        for (int hf = 0; hf < 2; hf++) {
            int row = m0 + mi*16 + rq + hf*8;
            float gm = fmaxf(fmaxf(pmax[row], pmax[96 + row]),
                             fmaxf(pmax[192 + row], pmax[288 + row]));
            float s = 0.f;
            #pragma unroll
            for (int nj = 0; nj < 3; nj++) {
                float e0 = __expf(acc[mi][nj][hf*2]     - gm);
                float e1 = __expf(acc[mi][nj][hf*2 + 1] - gm);
                acc[mi][nj][hf*2] = e0; acc[mi][nj][hf*2 + 1] = e1;
                s += e0 + e1;
            }
            s += __shfl_xor_sync(0xffffffffu, s, 1);
            s += __shfl_xor_sync(0xffffffffu, s, 2);
            if ((lane & 3) == 0) psum[warpN*96 + row] = s;
        }
    }
    __syncthreads();
    {
        __half* sA = (__half*)(sma + AOFF_A);
        #pragma unroll
        for (int mi = 0; mi < 3; mi++) {
            #pragma unroll
            for (int hf = 0; hf < 2; hf++) {
                int row = m0 + mi*16 + rq + hf*8;
                float tot = psum[row] + psum[96 + row] + psum[192 + row] + psum[288 + row];
                float inv = 1.0f / tot;
                #pragma unroll
                for (int nj = 0; nj < 3; nj++) {
                    __half2 a2 = __floats2half2_rn(acc[mi][nj][hf*2] * inv,
                                                   acc[mi][nj][hf*2 + 1] * inv);
                    *(__half2*)&sA[row*(APITCH/2) + n0 + nj*8 + c2] = a2;
                }
            }
        }
    }
    CP_WAIT0();          // V fully resident
    __syncthreads();     // sA visible + V visible to all warps

    // ---- AV: O[h,c] = A·Vh; 4 resident chunks, warp tile 48m x 16n
    __half* Og = g_Ot + (size_t)bw*HH*CC;
    int cW = warpN * 16;
    int vseg = warpN * 2;

    #pragma unroll
    for (int ck = 0; ck < 4; ck++) {
        uint32_t vBase = sb + AOFF_V + (uint32_t)(ck*12288);
        float vacc[3][2][4] = {};
        #pragma unroll
        for (int ks = 0; ks < 6; ks++) {
            uint32_t af[3][4], bh4[4];
            #pragma unroll
            for (int mi = 0; mi < 3; mi++) {
                int row = m0 + (lane & 15) + mi*16;
                ldsm_x4(af[mi], sb + AOFF_A + (uint32_t)(row*APITCH + ks*32 + (lane >> 4)*16));
            }
            {
                int row = ks*16 + (lane & 15);
                int seg = (vseg + (lane >> 4)) ^ swz;
                ldsm_x4t(bh4, vBase + (uint32_t)(row*128 + seg*16));
            }
            #pragma unroll
            for (int mi = 0; mi < 3; mi++) {
                mma_h(vacc[mi][0], af[mi], &bh4[0]);
                mma_h(vacc[mi][1], af[mi], &bh4[2]);
            }
        }
        __syncthreads();   // previous chunk's sO readers done

        __half* sO = (__half*)(sma + AOFF_O);   // pitch 72 halfs
        #pragma unroll
        for (int mi = 0; mi < 3; mi++)
            #pragma unroll
            for (int ni = 0; ni < 2; ni++) {
                int row = m0 + mi*16 + rq, col = cW + ni*8 + c2;
                *(__half2*)&sO[row*72 + col]     = __floats2half2_rn(vacc[mi][ni][0], vacc[mi][ni][1]);
                *(__half2*)&sO[(row+8)*72 + col] = __floats2half2_rn(vacc[mi][ni][2], vacc[mi][ni][3]);
            }
        __syncthreads();

        for (int i = tid; i < 768; i += 256) {
            int h = i >> 3, c8 = (i & 7) * 8;
            *(uint4*)&Og[(size_t)h*CC + ck*64 + c8] = *(uint4*)&sO[h*72 + c8];
        }
    }
}

// ---------------- kernel 3: transpose back + residual (coalesced Ot reads) ---
__global__ __launch_bounds__(256) void out_kernel(const float* __restrict__ x,
                                                  const float* __restrict__ gamma,
                                                  float* __restrict__ out) {
    __shared__ float tile[32][66];
    int c0 = blockIdx.x * 64;
    int w0 = blockIdx.y * 32;
    int bh = blockIdx.z;
    int b = bh / HH, h = bh % HH;
    int tid = threadIdx.x;
    float gm = gamma[0];
    const __half* Ob = g_Ot + (size_t)b * WW * HH * CC;
    {
        int wl = tid >> 3, cs = (tid & 7) * 8;
        uint4 v = *(const uint4*)(Ob + (size_t)((w0 + wl)*HH + h)*CC + c0 + cs);
        __half2* hp = (__half2*)&v;
        #pragma unroll
        for (int i = 0; i < 4; i++) {
            float2 f = __half22float2(hp[i]);
            *(float2*)&tile[wl][cs + i*2] = f;
        }
    }
    __syncthreads();
    {
        int cl = tid >> 2, ws = (tid & 3) * 8;
        size_t base = (size_t)b*CC*PP + (size_t)(c0 + cl)*PP + (size_t)h*WW + w0 + ws;
        float4 x0 = *(const float4*)&x[base];
        float4 x1 = *(const float4*)&x[base + 4];
        float4 o0, o1;
        o0.x = gm*tile[ws+0][cl] + x0.x;
        o0.y = gm*tile[ws+1][cl] + x0.y;
        o0.z = gm*tile[ws+2][cl] + x0.z;
        o0.w = gm*tile[ws+3][cl] + x0.w;
        o1.x = gm*tile[ws+4][cl] + x1.x;
        o1.y = gm*tile[ws+5][cl] + x1.y;
        o1.z = gm*tile[ws+6][cl] + x1.z;
        o1.w = gm*tile[ws+7][cl] + x1.w;
        *(float4*)&out[base]     = o0;
        *(float4*)&out[base + 4] = o1;
    }
}

// ---------------- launcher ---------------------------------------------------
extern "C" void kernel_launch(void* const* d_in, const int* in_sizes, int n_in,
                              void* d_out, int out_size) {
    const float* x     = (const float*)d_in[0];
    const float* Wq    = (const float*)d_in[1];
    const float* bq    = (const float*)d_in[2];
    const float* Wk    = (const float*)d_in[3];
    const float* bk    = (const float*)d_in[4];
    const float* Wv    = (const float*)d_in[5];
    const float* bv    = (const float*)d_in[6];
    const float* gamma = (const float*)d_in[7];
    float* out = (float*)d_out;

    cudaFuncSetAttribute(qkv_mma_kernel, cudaFuncAttributeMaxDynamicSharedMemorySize, QKV_SMEM);
    cudaFuncSetAttribute(attn_mma_kernel, cudaFuncAttributeMaxDynamicSharedMemorySize, ATT_SMEM);

    prep_kernel<<<(JTOT*CC + 255)/256, 256>>>(Wq, bq, Wk, bk, Wv, bv);
    qkv_mma_kernel<<<dim3(PP/64, BB), 256, QKV_SMEM>>>(x);
    attn_mma_kernel<<<dim3(BB*WW), 256, ATT_SMEM>>>();
    out_kernel<<<dim3(CC/64, WW/32, BB*HH), dim3(256)>>>(x, gamma, out);
}

// round 15
// speedup vs baseline: 1.7543x; 1.0910x over previous
#include <cuda_runtime.h>
#include <cuda_fp16.h>
#include <cstdint>

#define BB 16
#define CC 256
#define HH 96
#define WW 96
#define QKD 64
#define PP (HH*WW)          // 9216
#define JTOT 384

// ---------------- scratch (static device memory; no allocs allowed) ----------
__device__ float g_bcat[JTOT];
__device__ __half g_Whi[JTOT*CC];
__device__ __half g_Qhi[(size_t)BB*WW*HH*QKD];      // Q single fp16
__device__ __half g_Khi[(size_t)BB*WW*HH*QKD];      // K single fp16
__device__ __half g_Vhi[(size_t)BB*WW*HH*CC];       // V single fp16
__device__ __half g_Ot[(size_t)BB*WW*HH*CC];        // [b][w][h][c]  fp16

// ---------------- PTX helpers (baseline, sm_103-safe) ------------------------
__device__ __forceinline__ uint32_t smem_u32(const void* p) {
    uint32_t a;
    asm("{ .reg .u64 t; cvta.to.shared.u64 t, %1; cvt.u32.u64 %0, t; }" : "=r"(a) : "l"(p));
    return a;
}
__device__ __forceinline__ void ldsm_x4(uint32_t* r, uint32_t addr) {
    asm volatile("ldmatrix.sync.aligned.m8n8.x4.shared.b16 {%0,%1,%2,%3}, [%4];"
        : "=r"(r[0]), "=r"(r[1]), "=r"(r[2]), "=r"(r[3]) : "r"(addr));
}
__device__ __forceinline__ void ldsm_x4t(uint32_t* r, uint32_t addr) {
    asm volatile("ldmatrix.sync.aligned.m8n8.x4.trans.shared.b16 {%0,%1,%2,%3}, [%4];"
        : "=r"(r[0]), "=r"(r[1]), "=r"(r[2]), "=r"(r[3]) : "r"(addr));
}
__device__ __forceinline__ void ldsm_x2(uint32_t* r, uint32_t addr) {
    asm volatile("ldmatrix.sync.aligned.m8n8.x2.shared.b16 {%0,%1}, [%2];"
        : "=r"(r[0]), "=r"(r[1]) : "r"(addr));
}
__device__ __forceinline__ void mma_h(float* d, const uint32_t* a, const uint32_t* b) {
    asm volatile("mma.sync.aligned.m16n8k16.row.col.f32.f16.f16.f32 "
        "{%0,%1,%2,%3}, {%4,%5,%6,%7}, {%8,%9}, {%0,%1,%2,%3};"
        : "+f"(d[0]), "+f"(d[1]), "+f"(d[2]), "+f"(d[3])
        : "r"(a[0]), "r"(a[1]), "r"(a[2]), "r"(a[3]), "r"(b[0]), "r"(b[1]));
}
#define CP_ASYNC16(dst, src) \
    asm volatile("cp.async.cg.shared.global [%0], [%1], 16;" :: "r"(dst), "l"(src))
#define CP_COMMIT() asm volatile("cp.async.commit_group;" ::: "memory")
#define CP_WAIT0()  asm volatile("cp.async.wait_group 0;" ::: "memory")

// ---------------- kernel 0: weight concat (fp16 hi only) ---------------------
__global__ void prep_kernel(const float* __restrict__ Wq, const float* __restrict__ bq,
                            const float* __restrict__ Wk, const float* __restrict__ bk,
                            const float* __restrict__ Wv, const float* __restrict__ bv) {
    int i = blockIdx.x * blockDim.x + threadIdx.x;
    if (i < JTOT*CC) {
        int j = i / CC, k = i % CC;
        float v;
        if (j < 64)       v = Wq[j*CC + k];
        else if (j < 128) v = Wk[(j-64)*CC + k];
        else              v = Wv[(j-128)*CC + k];
        g_Whi[i] = __float2half_rn(v);
    }
    if (i < JTOT) {
        g_bcat[i] = (i < 64) ? bq[i] : (i < 128) ? bk[i-64] : bv[i-128];
    }
}

// ---------------- kernel 1: QKV projection (fp16 warp MMA, 1-pass) -----------
// Bias folded into fragments; light fp16-emitting epilogue.
#define OFF_BH   0          // 32768
#define OFF_A    32768      // 2 x 8192
#define OFF_STG  49152      // 64 x 68 fp32 = 17408
#define OFF_BIAS 66560      // 1536
#define QKV_SMEM 68096
#define STGP 68

__global__ __launch_bounds__(256, 3) void qkv_mma_kernel(const float* __restrict__ x) {
    extern __shared__ __align__(128) char smq[];
    uint32_t sb = smem_u32(smq);
    int tid = threadIdx.x, wid = tid >> 5, lane = tid & 31;
    int pBase = blockIdx.x * 64;
    int bz = blockIdx.y;
    int warpM = wid & 1, warpN = wid >> 1;   // 2 x 4
    int jW = warpM * 32, pW = warpN * 16;

    for (int t = tid; t < JTOT; t += 256)
        *(float*)(smq + OFF_BIAS + t*4) = g_bcat[t];

    // A chunk 0 -> buf0
    for (int t = tid; t < 512; t += 256) {
        int j = t >> 3, sg = t & 7;
        uint32_t sw = (uint32_t)(j*128 + ((sg ^ (j & 7))*16));
        CP_ASYNC16(sb + OFF_A + sw, g_Whi + j*CC + sg*8);
    }
    CP_COMMIT();

    // B resident: fp32 x -> fp16, swizzled 128B rows
    {
        const float* xb = x + (size_t)bz*CC*PP;
        for (int t = tid; t < 4096; t += 256) {
            int k = t >> 4, sg = t & 15;
            float4 v = *(const float4*)&xb[(size_t)k*PP + pBase + sg*4];
            __half2 h0 = __float22half2_rn(make_float2(v.x, v.y));
            __half2 h1 = __float22half2_rn(make_float2(v.z, v.w));
            uint32_t sw = (uint32_t)(k*128 + (((sg>>1) ^ (k & 7))*16) + (sg&1)*8);
            *(uint2*)(smq + OFF_BH + sw) = make_uint2(*(uint32_t*)&h0, *(uint32_t*)&h1);
        }
    }

    int rA   = lane & 15;
    int swzA = rA & 7;
    int aseg = lane >> 4;
    int swzB = lane & 7;
    int bseg = (pW >> 3);
    int rq = lane >> 2, c2 = (lane & 3) * 2;

    for (int jt = 0; jt < 6; jt++) {
        float acc[2][2][4] = {};

        for (int ch = 0; ch < 4; ch++) {
            CP_WAIT0();
            __syncthreads();
            int nit = jt*4 + ch + 1;
            if (nit < 24) {
                int njt = nit >> 2, nch = nit & 3;
                uint32_t dst = sb + OFF_A + (uint32_t)((nit & 1) * 8192);
                const __half* sH = g_Whi + (njt*64)*CC + nch*64;
                for (int t = tid; t < 512; t += 256) {
                    int j = t >> 3, sg = t & 7;
                    uint32_t sw = (uint32_t)(j*128 + ((sg ^ (j & 7))*16));
                    CP_ASYNC16(dst + sw, sH + j*CC + sg*8);
                }
                CP_COMMIT();
            }
            uint32_t aBufH = sb + OFF_A + (uint32_t)(((jt*4 + ch) & 1) * 8192);

            #pragma unroll
            for (int ksc = 0; ksc < 4; ksc++) {
                int ks16 = ch*4 + ksc;
                uint32_t brow = (uint32_t)((ks16*16 + rA)*128 + (((bseg + aseg) ^ swzB)*16));
                uint32_t ah[2][4], bh4[4];
                #pragma unroll
                for (int mi = 0; mi < 2; mi++) {
                    int row = jW + rA + mi*16;
                    ldsm_x4(ah[mi], aBufH + (uint32_t)(row*128 + (((ksc*2 + aseg) ^ swzA)*16)));
                }
                ldsm_x4t(bh4, sb + OFF_BH + brow);
                #pragma unroll
                for (int mi = 0; mi < 2; mi++) {
                    mma_h(acc[mi][0], ah[mi], &bh4[0]);
                    mma_h(acc[mi][1], ah[mi], &bh4[2]);
                }
            }
        }

        // ---- bias into fragments (row-dependent only)
        {
            const float* sBias = (const float*)(smq + OFF_BIAS) + jt*64;
            float b00 = sBias[jW + rq],      b01 = sBias[jW + rq + 8];
            float b10 = sBias[jW + 16 + rq], b11 = sBias[jW + 24 + rq];
            #pragma unroll
            for (int ni = 0; ni < 2; ni++) {
                acc[0][ni][0] += b00; acc[0][ni][1] += b00;
                acc[0][ni][2] += b01; acc[0][ni][3] += b01;
                acc[1][ni][0] += b10; acc[1][ni][1] += b10;
                acc[1][ni][2] += b11; acc[1][ni][3] += b11;
            }
        }

        // ---- stage [p][j] fp32 (pitch 68, 16B-aligned rows)
        float* stg = (float*)(smq + OFF_STG);
        #pragma unroll
        for (int mi = 0; mi < 2; mi++)
            #pragma unroll
            for (int ni = 0; ni < 2; ni++) {
                int j = jW + mi*16 + rq;
                int p = pW + ni*8 + c2;
                stg[p*STGP + j]         = acc[mi][ni][0];
                stg[(p+1)*STGP + j]     = acc[mi][ni][1];
                stg[p*STGP + j + 8]     = acc[mi][ni][2];
                stg[(p+1)*STGP + j + 8] = acc[mi][ni][3];
            }
        __syncthreads();

        // ---- light epilogue: 4 iters of LDS.128 + cvt + STG.64
        #pragma unroll
        for (int k4 = 0; k4 < 4; k4++) {
            int idx = tid + k4*256;
            int pl = idx >> 4, jq = (idx & 15) * 4;
            float4 v = *(const float4*)&stg[pl*STGP + jq];
            __half2 h0 = __float22half2_rn(make_float2(v.x, v.y));
            __half2 h1 = __float22half2_rn(make_float2(v.z, v.w));
            uint2 hv = make_uint2(*(uint32_t*)&h0, *(uint32_t*)&h1);
            int p = pBase + pl;
            int h = p / WW, w = p - h*WW;
            size_t col = (size_t)(bz*WW + w)*HH + h;
            if (jt == 0)      *(uint2*)(g_Qhi + col*QKD + jq) = hv;
            else if (jt == 1) *(uint2*)(g_Khi + col*QKD + jq) = hv;
            else              *(uint2*)(g_Vhi + col*CC + (jt-2)*64 + jq) = hv;
        }
        __syncthreads();
    }
}

// ---------------- kernel 2: per-(b,w) column attention ------------------------
// V prefetched at entry; AV warp tile 48m x 32c, 2 iterations.
// LAYOUT FIX vs round 14: V starts AFTER the full K region (no overlap).
#define AOFF_Q   0          // 12288
#define AOFF_K   12288      // 12288 (ends 24576)
#define AOFF_A   0          // fp16 96x104 (19968) overlays Q + dead K head
#define AOFF_V   24576      // 4 chunks x 12288 = 49152 (ends 73728)
#define AOFF_O   73728      // fp16 96x136 = 26112 (ends 99840)
#define AOFF_STAT 99840     // 3072 (ends 102912)
#define ATT_SMEM 102912
#define APITCH 208
#define OPITCH 136

__global__ __launch_bounds__(256) void attn_mma_kernel() {
    extern __shared__ __align__(128) char sma[];
    uint32_t sb = smem_u32(sma);
    int tid = threadIdx.x, wid = tid >> 5, lane = tid & 31;
    int bw = blockIdx.x;
    int swz = lane & 7;

    // ---- prefetch ALL of V via cp.async (overlaps scores/softmax)
    {
        const __half* Vh = g_Vhi + (size_t)bw*HH*CC;
        for (int t = tid; t < 3072; t += 256) {
            int g = t >> 5, cseg = t & 31;
            int ck = cseg >> 3, sg = cseg & 7;
            uint32_t dst = sb + AOFF_V + (uint32_t)(ck*12288 + g*128 + ((sg ^ (g & 7))*16));
            CP_ASYNC16(dst, Vh + (size_t)g*CC + cseg*8);
        }
        CP_COMMIT();
    }

    // ---- stage Qh, Kh (swizzled 128B rows)
    {
        const __half* Qh = g_Qhi + (size_t)bw*HH*QKD;
        const __half* Kh = g_Khi + (size_t)bw*HH*QKD;
        for (int i = tid; i < 768; i += 256) {
            int h = i >> 3, sg = i & 7;
            uint32_t sw = (uint32_t)(h*128 + ((sg ^ (h & 7))*16));
            int go = h*QKD + sg*8;
            *(uint4*)(sma + AOFF_Q + sw) = *(const uint4*)(Qh + go);
            *(uint4*)(sma + AOFF_K + sw) = *(const uint4*)(Kh + go);
        }
    }
    __syncthreads();

    int warpM = wid & 1, warpN = wid >> 1;
    int m0 = warpM * 48;
    int n0 = warpN * 24;
    int rq = lane >> 2, c2 = (lane & 3) * 2;

    // ---- scores: register-resident, warp tile 48m x 24n, 1 pass
    float acc[3][3][4] = {};
    #pragma unroll
    for (int ks = 0; ks < 4; ks++) {
        uint32_t af[3][4], bf4[4], bf2[2];
        #pragma unroll
        for (int mi = 0; mi < 3; mi++) {
            int row = m0 + (lane & 15) + mi*16;
            ldsm_x4(af[mi], sb + AOFF_Q + (uint32_t)(row*128 + (((ks*2 + (lane >> 4)) ^ swz)*16)));
        }
        {
            int row = n0 + ((lane >> 4) << 3) + (lane & 7);
            int seg = (ks*2 + ((lane >> 3) & 1)) ^ swz;
            ldsm_x4(bf4, sb + AOFF_K + (uint32_t)(row*128 + seg*16));
        }
        {
            int row = n0 + 16 + (lane & 7);
            int seg = (ks*2 + ((lane >> 3) & 1)) ^ swz;
            ldsm_x2(bf2, sb + AOFF_K + (uint32_t)(row*128 + seg*16));
        }
        #pragma unroll
        for (int mi = 0; mi < 3; mi++) {
            mma_h(acc[mi][0], af[mi], &bf4[0]);
            mma_h(acc[mi][1], af[mi], &bf4[2]);
            mma_h(acc[mi][2], af[mi], bf2);
        }
    }

    // ---- softmax
    float* pmax = (float*)(sma + AOFF_STAT);
    float* psum = (float*)(sma + AOFF_STAT + 1536);
    #pragma unroll
    for (int mi = 0; mi < 3; mi++) {
        float m0v = fmaxf(fmaxf(acc[mi][0][0], acc[mi][0][1]),
                          fmaxf(acc[mi][1][0], acc[mi][1][1]));
        m0v = fmaxf(m0v, fmaxf(acc[mi][2][0], acc[mi][2][1]));
        float m1v = fmaxf(fmaxf(acc[mi][0][2], acc[mi][0][3]),
                          fmaxf(acc[mi][1][2], acc[mi][1][3]));
        m1v = fmaxf(m1v, fmaxf(acc[mi][2][2], acc[mi][2][3]));
        m0v = fmaxf(m0v, __shfl_xor_sync(0xffffffffu, m0v, 1));
        m0v = fmaxf(m0v, __shfl_xor_sync(0xffffffffu, m0v, 2));
        m1v = fmaxf(m1v, __shfl_xor_sync(0xffffffffu, m1v, 1));
        m1v = fmaxf(m1v, __shfl_xor_sync(0xffffffffu, m1v, 2));
        if ((lane & 3) == 0) {
            pmax[warpN*96 + m0 + mi*16 + rq]     = m0v;
            pmax[warpN*96 + m0 + mi*16 + rq + 8] = m1v;
        }
    }
    __syncthreads();
    #pragma unroll
    for (int mi = 0; mi < 3; mi++) {
        #pragma unroll
        for (int hf = 0; hf < 2; hf++) {
            int row = m0 + mi*16 + rq + hf*8;
            float gm = fmaxf(fmaxf(pmax[row], pmax[96 + row]),
                             fmaxf(pmax[192 + row], pmax[288 + row]));
            float s = 0.f;
            #pragma unroll
            for (int nj = 0; nj < 3; nj++) {
                float e0 = __expf(acc[mi][nj][hf*2]     - gm);
                float e1 = __expf(acc[mi][nj][hf*2 + 1] - gm);
                acc[mi][nj][hf*2] = e0; acc[mi][nj][hf*2 + 1] = e1;
                s += e0 + e1;
            }
            s += __shfl_xor_sync(0xffffffffu, s, 1);
            s += __shfl_xor_sync(0xffffffffu, s, 2);
            if ((lane & 3) == 0) psum[warpN*96 + row] = s;
        }
    }
    __syncthreads();
    {
        __half* sA = (__half*)(sma + AOFF_A);
        #pragma unroll
        for (int mi = 0; mi < 3; mi++) {
            #pragma unroll
            for (int hf = 0; hf < 2; hf++) {
                int row = m0 + mi*16 + rq + hf*8;
                float tot = psum[row] + psum[96 + row] + psum[192 + row] + psum[288 + row];
                float inv = 1.0f / tot;
                #pragma unroll
                for (int nj = 0; nj < 3; nj++) {
                    __half2 a2 = __floats2half2_rn(acc[mi][nj][hf*2] * inv,
                                                   acc[mi][nj][hf*2 + 1] * inv);
                    *(__half2*)&sA[row*(APITCH/2) + n0 + nj*8 + c2] = a2;
                }
            }
        }
    }
    CP_WAIT0();
    __syncthreads();

    // ---- AV: warp tile 48m x 32c, 2 iterations over c halves of 128
    __half* Og = g_Ot + (size_t)bw*HH*CC;
    int cwBase = (warpN & 1) * 32;              // col offset inside the 64-col chunk
    int s0base = (warpN & 1) * 4;               // seg base inside chunk

    #pragma unroll
    for (int it = 0; it < 2; it++) {
        int ck = it*2 + (warpN >> 1);
        uint32_t vBase = sb + AOFF_V + (uint32_t)(ck*12288);
        float vacc[3][4][4] = {};
        #pragma unroll
        for (int ks = 0; ks < 6; ks++) {
            uint32_t af[3][4], b04[4], b14[4];
            #pragma unroll
            for (int mi = 0; mi < 3; mi++) {
                int row = m0 + (lane & 15) + mi*16;
                ldsm_x4(af[mi], sb + AOFF_A + (uint32_t)(row*APITCH + ks*32 + (lane >> 4)*16));
            }
            {
                int row = ks*16 + (lane & 15);
                int s0 = s0base + (lane >> 4);
                ldsm_x4t(b04, vBase + (uint32_t)(row*128 + ((s0 ^ swz)*16)));
                ldsm_x4t(b14, vBase + (uint32_t)(row*128 + (((s0 + 2) ^ swz)*16)));
            }
            #pragma unroll
            for (int mi = 0; mi < 3; mi++) {
                mma_h(vacc[mi][0], af[mi], &b04[0]);
                mma_h(vacc[mi][1], af[mi], &b04[2]);
                mma_h(vacc[mi][2], af[mi], &b14[0]);
                mma_h(vacc[mi][3], af[mi], &b14[2]);
            }
        }
        __syncthreads();   // previous iteration's sO readers done

        __half* sO = (__half*)(sma + AOFF_O);   // [96][136] halfs, holds 128 c
        int colW = (warpN >> 1) * 64 + cwBase;  // warp col base within the 128
        #pragma unroll
        for (int mi = 0; mi < 3; mi++)
            #pragma unroll
            for (int ni = 0; ni < 4; ni++) {
                int row = m0 + mi*16 + rq, col = colW + ni*8 + c2;
                *(__half2*)&sO[row*OPITCH + col]     = __floats2half2_rn(vacc[mi][ni][0], vacc[mi][ni][1]);
                *(__half2*)&sO[(row+8)*OPITCH + col] = __floats2half2_rn(vacc[mi][ni][2], vacc[mi][ni][3]);
            }
        __syncthreads();

        for (int i = tid; i < 1536; i += 256) {
            int h = i >> 4, c8 = (i & 15) * 8;
            *(uint4*)&Og[(size_t)h*CC + it*128 + c8] = *(uint4*)&sO[h*OPITCH + c8];
        }
    }
}

// ---------------- kernel 3: transpose back + residual (coalesced Ot reads) ---
__global__ __launch_bounds__(256) void out_kernel(const float* __restrict__ x,
                                                  const float* __restrict__ gamma,
                                                  float* __restrict__ out) {
    __shared__ float tile[32][66];
    int c0 = blockIdx.x * 64;
    int w0 = blockIdx.y * 32;
    int bh = blockIdx.z;
    int b = bh / HH, h = bh % HH;
    int tid = threadIdx.x;
    float gm = gamma[0];
    const __half* Ob = g_Ot + (size_t)b * WW * HH * CC;
    {
        int wl = tid >> 3, cs = (tid & 7) * 8;
        uint4 v = *(const uint4*)(Ob + (size_t)((w0 + wl)*HH + h)*CC + c0 + cs);
        __half2* hp = (__half2*)&v;
        #pragma unroll
        for (int i = 0; i < 4; i++) {
            float2 f = __half22float2(hp[i]);
            *(float2*)&tile[wl][cs + i*2] = f;
        }
    }
    __syncthreads();
    {
        int cl = tid >> 2, ws = (tid & 3) * 8;
        size_t base = (size_t)b*CC*PP + (size_t)(c0 + cl)*PP + (size_t)h*WW + w0 + ws;
        float4 x0 = *(const float4*)&x[base];
        float4 x1 = *(const float4*)&x[base + 4];
        float4 o0, o1;
        o0.x = gm*tile[ws+0][cl] + x0.x;
        o0.y = gm*tile[ws+1][cl] + x0.y;
        o0.z = gm*tile[ws+2][cl] + x0.z;
        o0.w = gm*tile[ws+3][cl] + x0.w;
        o1.x = gm*tile[ws+4][cl] + x1.x;
        o1.y = gm*tile[ws+5][cl] + x1.y;
        o1.z = gm*tile[ws+6][cl] + x1.z;
        o1.w = gm*tile[ws+7][cl] + x1.w;
        *(float4*)&out[base]     = o0;
        *(float4*)&out[base + 4] = o1;
    }
}

// ---------------- launcher ---------------------------------------------------
extern "C" void kernel_launch(void* const* d_in, const int* in_sizes, int n_in,
                              void* d_out, int out_size) {
    const float* x     = (const float*)d_in[0];
    const float* Wq    = (const float*)d_in[1];
    const float* bq    = (const float*)d_in[2];
    const float* Wk    = (const float*)d_in[3];
    const float* bk    = (const float*)d_in[4];
    const float* Wv    = (const float*)d_in[5];
    const float* bv    = (const float*)d_in[6];
    const float* gamma = (const float*)d_in[7];
    float* out = (float*)d_out;

    cudaFuncSetAttribute(qkv_mma_kernel, cudaFuncAttributeMaxDynamicSharedMemorySize, QKV_SMEM);
    cudaFuncSetAttribute(attn_mma_kernel, cudaFuncAttributeMaxDynamicSharedMemorySize, ATT_SMEM);

    prep_kernel<<<(JTOT*CC + 255)/256, 256>>>(Wq, bq, Wk, bk, Wv, bv);
    qkv_mma_kernel<<<dim3(PP/64, BB), 256, QKV_SMEM>>>(x);
    attn_mma_kernel<<<dim3(BB*WW), 256, ATT_SMEM>>>();
    out_kernel<<<dim3(CC/64, WW/32, BB*HH), dim3(256)>>>(x, gamma, out);
}

// round 16
// speedup vs baseline: 1.8043x; 1.0285x over previous
#include <cuda_runtime.h>
#include <cuda_fp16.h>
#include <cstdint>

#define BB 16
#define CC 256
#define HH 96
#define WW 96
#define QKD 64
#define PP (HH*WW)          // 9216
#define JTOT 384

// ---------------- scratch (static device memory; no allocs allowed) ----------
__device__ float g_bcat[JTOT];
__device__ __half g_Whi[JTOT*CC];
__device__ __half g_Qhi[(size_t)BB*WW*HH*QKD];      // Q single fp16
__device__ __half g_Khi[(size_t)BB*WW*HH*QKD];      // K single fp16
__device__ __half g_Vhi[(size_t)BB*WW*HH*CC];       // V single fp16
__device__ __half g_Ot[(size_t)BB*WW*HH*CC];        // [b][w][h][c]  fp16

// ---------------- PTX helpers (baseline, sm_103-safe) ------------------------
__device__ __forceinline__ uint32_t smem_u32(const void* p) {
    uint32_t a;
    asm("{ .reg .u64 t; cvta.to.shared.u64 t, %1; cvt.u32.u64 %0, t; }" : "=r"(a) : "l"(p));
    return a;
}
__device__ __forceinline__ void ldsm_x4(uint32_t* r, uint32_t addr) {
    asm volatile("ldmatrix.sync.aligned.m8n8.x4.shared.b16 {%0,%1,%2,%3}, [%4];"
        : "=r"(r[0]), "=r"(r[1]), "=r"(r[2]), "=r"(r[3]) : "r"(addr));
}
__device__ __forceinline__ void ldsm_x4t(uint32_t* r, uint32_t addr) {
    asm volatile("ldmatrix.sync.aligned.m8n8.x4.trans.shared.b16 {%0,%1,%2,%3}, [%4];"
        : "=r"(r[0]), "=r"(r[1]), "=r"(r[2]), "=r"(r[3]) : "r"(addr));
}
__device__ __forceinline__ void ldsm_x2(uint32_t* r, uint32_t addr) {
    asm volatile("ldmatrix.sync.aligned.m8n8.x2.shared.b16 {%0,%1}, [%2];"
        : "=r"(r[0]), "=r"(r[1]) : "r"(addr));
}
__device__ __forceinline__ void mma_h(float* d, const uint32_t* a, const uint32_t* b) {
    asm volatile("mma.sync.aligned.m16n8k16.row.col.f32.f16.f16.f32 "
        "{%0,%1,%2,%3}, {%4,%5,%6,%7}, {%8,%9}, {%0,%1,%2,%3};"
        : "+f"(d[0]), "+f"(d[1]), "+f"(d[2]), "+f"(d[3])
        : "r"(a[0]), "r"(a[1]), "r"(a[2]), "r"(a[3]), "r"(b[0]), "r"(b[1]));
}
#define CP_ASYNC16(dst, src) \
    asm volatile("cp.async.cg.shared.global [%0], [%1], 16;" :: "r"(dst), "l"(src))
#define CP_COMMIT() asm volatile("cp.async.commit_group;" ::: "memory")
#define CP_WAIT0()  asm volatile("cp.async.wait_group 0;" ::: "memory")
#define CP_WAIT1()  asm volatile("cp.async.wait_group 1;" ::: "memory")

// ---------------- kernel 0: weight concat (fp16 hi only) ---------------------
__global__ void prep_kernel(const float* __restrict__ Wq, const float* __restrict__ bq,
                            const float* __restrict__ Wk, const float* __restrict__ bk,
                            const float* __restrict__ Wv, const float* __restrict__ bv) {
    int i = blockIdx.x * blockDim.x + threadIdx.x;
    if (i < JTOT*CC) {
        int j = i / CC, k = i % CC;
        float v;
        if (j < 64)       v = Wq[j*CC + k];
        else if (j < 128) v = Wk[(j-64)*CC + k];
        else              v = Wv[(j-128)*CC + k];
        g_Whi[i] = __float2half_rn(v);
    }
    if (i < JTOT) {
        g_bcat[i] = (i < 64) ? bq[i] : (i < 128) ? bk[i-64] : bv[i-128];
    }
}

// ---------------- kernel 1: QKV projection (fp16 warp MMA, 1-pass) -----------
// Triple-buffered A pipeline (depth 2); bias folded; light fp16 epilogue.
#define OFF_BH   0          // 32768
#define OFF_A    32768      // 3 x 8192 = 24576
#define OFF_STG  57344      // 64 x 68 fp32 = 17408
#define OFF_BIAS 74752      // 1536
#define QKV_SMEM 76288
#define STGP 68

__global__ __launch_bounds__(256, 3) void qkv_mma_kernel(const float* __restrict__ x) {
    extern __shared__ __align__(128) char smq[];
    uint32_t sb = smem_u32(smq);
    int tid = threadIdx.x, wid = tid >> 5, lane = tid & 31;
    int pBase = blockIdx.x * 64;
    int bz = blockIdx.y;
    int warpM = wid & 1, warpN = wid >> 1;   // 2 x 4
    int jW = warpM * 32, pW = warpN * 16;

    for (int t = tid; t < JTOT; t += 256)
        *(float*)(smq + OFF_BIAS + t*4) = g_bcat[t];

    // A chunks 0 and 1 -> bufs 0,1 (two committed groups)
    #pragma unroll
    for (int pre = 0; pre < 2; pre++) {
        const __half* sH = g_Whi + pre*64;   // jt=0, ch=pre
        uint32_t dst = sb + OFF_A + (uint32_t)(pre * 8192);
        for (int t = tid; t < 512; t += 256) {
            int j = t >> 3, sg = t & 7;
            uint32_t sw = (uint32_t)(j*128 + ((sg ^ (j & 7))*16));
            CP_ASYNC16(dst + sw, sH + j*CC + sg*8);
        }
        CP_COMMIT();
    }

    // B resident: fp32 x -> fp16, swizzled 128B rows
    {
        const float* xb = x + (size_t)bz*CC*PP;
        for (int t = tid; t < 4096; t += 256) {
            int k = t >> 4, sg = t & 15;
            float4 v = *(const float4*)&xb[(size_t)k*PP + pBase + sg*4];
            __half2 h0 = __float22half2_rn(make_float2(v.x, v.y));
            __half2 h1 = __float22half2_rn(make_float2(v.z, v.w));
            uint32_t sw = (uint32_t)(k*128 + (((sg>>1) ^ (k & 7))*16) + (sg&1)*8);
            *(uint2*)(smq + OFF_BH + sw) = make_uint2(*(uint32_t*)&h0, *(uint32_t*)&h1);
        }
    }

    int rA   = lane & 15;
    int swzA = rA & 7;
    int aseg = lane >> 4;
    int swzB = lane & 7;
    int bseg = (pW >> 3);
    int rq = lane >> 2, c2 = (lane & 3) * 2;

    for (int jt = 0; jt < 6; jt++) {
        float acc[2][2][4] = {};

        for (int ch = 0; ch < 4; ch++) {
            int it = jt*4 + ch;
            if (it == 23) { CP_WAIT0(); } else { CP_WAIT1(); }   // A_it resident
            __syncthreads();
            int nit = it + 2;
            if (nit < 24) {
                int njt = nit >> 2, nch = nit & 3;
                uint32_t dst = sb + OFF_A + (uint32_t)((nit % 3) * 8192);
                const __half* sH = g_Whi + (njt*64)*CC + nch*64;
                for (int t = tid; t < 512; t += 256) {
                    int j = t >> 3, sg = t & 7;
                    uint32_t sw = (uint32_t)(j*128 + ((sg ^ (j & 7))*16));
                    CP_ASYNC16(dst + sw, sH + j*CC + sg*8);
                }
                CP_COMMIT();
            }
            uint32_t aBufH = sb + OFF_A + (uint32_t)((it % 3) * 8192);

            #pragma unroll
            for (int ksc = 0; ksc < 4; ksc++) {
                int ks16 = ch*4 + ksc;
                uint32_t brow = (uint32_t)((ks16*16 + rA)*128 + (((bseg + aseg) ^ swzB)*16));
                uint32_t ah[2][4], bh4[4];
                #pragma unroll
                for (int mi = 0; mi < 2; mi++) {
                    int row = jW + rA + mi*16;
                    ldsm_x4(ah[mi], aBufH + (uint32_t)(row*128 + (((ksc*2 + aseg) ^ swzA)*16)));
                }
                ldsm_x4t(bh4, sb + OFF_BH + brow);
                #pragma unroll
                for (int mi = 0; mi < 2; mi++) {
                    mma_h(acc[mi][0], ah[mi], &bh4[0]);
                    mma_h(acc[mi][1], ah[mi], &bh4[2]);
                }
            }
        }

        // ---- bias into fragments (row-dependent only)
        {
            const float* sBias = (const float*)(smq + OFF_BIAS) + jt*64;
            float b00 = sBias[jW + rq],      b01 = sBias[jW + rq + 8];
            float b10 = sBias[jW + 16 + rq], b11 = sBias[jW + 24 + rq];
            #pragma unroll
            for (int ni = 0; ni < 2; ni++) {
                acc[0][ni][0] += b00; acc[0][ni][1] += b00;
                acc[0][ni][2] += b01; acc[0][ni][3] += b01;
                acc[1][ni][0] += b10; acc[1][ni][1] += b10;
                acc[1][ni][2] += b11; acc[1][ni][3] += b11;
            }
        }

        // ---- stage [p][j] fp32 (pitch 68)
        float* stg = (float*)(smq + OFF_STG);
        #pragma unroll
        for (int mi = 0; mi < 2; mi++)
            #pragma unroll
            for (int ni = 0; ni < 2; ni++) {
                int j = jW + mi*16 + rq;
                int p = pW + ni*8 + c2;
                stg[p*STGP + j]         = acc[mi][ni][0];
                stg[(p+1)*STGP + j]     = acc[mi][ni][1];
                stg[p*STGP + j + 8]     = acc[mi][ni][2];
                stg[(p+1)*STGP + j + 8] = acc[mi][ni][3];
            }
        __syncthreads();

        // ---- light epilogue
        #pragma unroll
        for (int k4 = 0; k4 < 4; k4++) {
            int idx = tid + k4*256;
            int pl = idx >> 4, jq = (idx & 15) * 4;
            float4 v = *(const float4*)&stg[pl*STGP + jq];
            __half2 h0 = __float22half2_rn(make_float2(v.x, v.y));
            __half2 h1 = __float22half2_rn(make_float2(v.z, v.w));
            uint2 hv = make_uint2(*(uint32_t*)&h0, *(uint32_t*)&h1);
            int p = pBase + pl;
            int h = p / WW, w = p - h*WW;
            size_t col = (size_t)(bz*WW + w)*HH + h;
            if (jt == 0)      *(uint2*)(g_Qhi + col*QKD + jq) = hv;
            else if (jt == 1) *(uint2*)(g_Khi + col*QKD + jq) = hv;
            else              *(uint2*)(g_Vhi + col*CC + (jt-2)*64 + jq) = hv;
        }
        __syncthreads();
    }
}

// ---------------- kernel 2: per-(b,w) column attention ------------------------
// Q/K cp.async group 1; V cp.async group 2 (streams through scores/softmax).
#define AOFF_Q   0          // 12288
#define AOFF_K   12288      // 12288 (ends 24576)
#define AOFF_A   0          // fp16 96x104 (19968) overlays Q + dead K head
#define AOFF_V   24576      // 4 chunks x 12288 = 49152 (ends 73728)
#define AOFF_O   73728      // fp16 96x136 = 26112 (ends 99840)
#define AOFF_STAT 99840     // 3072 (ends 102912)
#define ATT_SMEM 102912
#define APITCH 208
#define OPITCH 136

__global__ __launch_bounds__(256) void attn_mma_kernel() {
    extern __shared__ __align__(128) char sma[];
    uint32_t sb = smem_u32(sma);
    int tid = threadIdx.x, wid = tid >> 5, lane = tid & 31;
    int bw = blockIdx.x;
    int swz = lane & 7;

    // ---- stage Qh, Kh via cp.async (group 1 — needed first)
    {
        const __half* Qh = g_Qhi + (size_t)bw*HH*QKD;
        const __half* Kh = g_Khi + (size_t)bw*HH*QKD;
        for (int i = tid; i < 768; i += 256) {
            int h = i >> 3, sg = i & 7;
            uint32_t sw = (uint32_t)(h*128 + ((sg ^ (h & 7))*16));
            int go = h*QKD + sg*8;
            CP_ASYNC16(sb + AOFF_Q + sw, Qh + go);
            CP_ASYNC16(sb + AOFF_K + sw, Kh + go);
        }
        CP_COMMIT();
    }
    // ---- prefetch ALL of V (group 2 — streams during scores/softmax)
    {
        const __half* Vh = g_Vhi + (size_t)bw*HH*CC;
        for (int t = tid; t < 3072; t += 256) {
            int g = t >> 5, cseg = t & 31;
            int ck = cseg >> 3, sg = cseg & 7;
            uint32_t dst = sb + AOFF_V + (uint32_t)(ck*12288 + g*128 + ((sg ^ (g & 7))*16));
            CP_ASYNC16(dst, Vh + (size_t)g*CC + cseg*8);
        }
        CP_COMMIT();
    }
    CP_WAIT1();          // Q/K resident (V may still be in flight)
    __syncthreads();

    int warpM = wid & 1, warpN = wid >> 1;
    int m0 = warpM * 48;
    int n0 = warpN * 24;
    int rq = lane >> 2, c2 = (lane & 3) * 2;

    // ---- scores: register-resident, warp tile 48m x 24n, 1 pass
    float acc[3][3][4] = {};
    #pragma unroll
    for (int ks = 0; ks < 4; ks++) {
        uint32_t af[3][4], bf4[4], bf2[2];
        #pragma unroll
        for (int mi = 0; mi < 3; mi++) {
            int row = m0 + (lane & 15) + mi*16;
            ldsm_x4(af[mi], sb + AOFF_Q + (uint32_t)(row*128 + (((ks*2 + (lane >> 4)) ^ swz)*16)));
        }
        {
            int row = n0 + ((lane >> 4) << 3) + (lane & 7);
            int seg = (ks*2 + ((lane >> 3) & 1)) ^ swz;
            ldsm_x4(bf4, sb + AOFF_K + (uint32_t)(row*128 + seg*16));
        }
        {
            int row = n0 + 16 + (lane & 7);
            int seg = (ks*2 + ((lane >> 3) & 1)) ^ swz;
            ldsm_x2(bf2, sb + AOFF_K + (uint32_t)(row*128 + seg*16));
        }
        #pragma unroll
        for (int mi = 0; mi < 3; mi++) {
            mma_h(acc[mi][0], af[mi], &bf4[0]);
            mma_h(acc[mi][1], af[mi], &bf4[2]);
            mma_h(acc[mi][2], af[mi], bf2);
        }
    }

    // ---- softmax
    float* pmax = (float*)(sma + AOFF_STAT);
    float* psum = (float*)(sma + AOFF_STAT + 1536);
    #pragma unroll
    for (int mi = 0; mi < 3; mi++) {
        float m0v = fmaxf(fmaxf(acc[mi][0][0], acc[mi][0][1]),
                          fmaxf(acc[mi][1][0], acc[mi][1][1]));
        m0v = fmaxf(m0v, fmaxf(acc[mi][2][0], acc[mi][2][1]));
        float m1v = fmaxf(fmaxf(acc[mi][0][2], acc[mi][0][3]),
                          fmaxf(acc[mi][1][2], acc[mi][1][3]));
        m1v = fmaxf(m1v, fmaxf(acc[mi][2][2], acc[mi][2][3]));
        m0v = fmaxf(m0v, __shfl_xor_sync(0xffffffffu, m0v, 1));
        m0v = fmaxf(m0v, __shfl_xor_sync(0xffffffffu, m0v, 2));
        m1v = fmaxf(m1v, __shfl_xor_sync(0xffffffffu, m1v, 1));
        m1v = fmaxf(m1v, __shfl_xor_sync(0xffffffffu, m1v, 2));
        if ((lane & 3) == 0) {
            pmax[warpN*96 + m0 + mi*16 + rq]     = m0v;
            pmax[warpN*96 + m0 + mi*16 + rq + 8] = m1v;
        }
    }
    __syncthreads();
    #pragma unroll
    for (int mi = 0; mi < 3; mi++) {
        #pragma unroll
        for (int hf = 0; hf < 2; hf++) {
            int row = m0 + mi*16 + rq + hf*8;
            float gm = fmaxf(fmaxf(pmax[row], pmax[96 + row]),
                             fmaxf(pmax[192 + row], pmax[288 + row]));
            float s = 0.f;
            #pragma unroll
            for (int nj = 0; nj < 3; nj++) {
                float e0 = __expf(acc[mi][nj][hf*2]     - gm);
                float e1 = __expf(acc[mi][nj][hf*2 + 1] - gm);
                acc[mi][nj][hf*2] = e0; acc[mi][nj][hf*2 + 1] = e1;
                s += e0 + e1;
            }
            s += __shfl_xor_sync(0xffffffffu, s, 1);
            s += __shfl_xor_sync(0xffffffffu, s, 2);
            if ((lane & 3) == 0) psum[warpN*96 + row] = s;
        }
    }
    __syncthreads();
    {
        __half* sA = (__half*)(sma + AOFF_A);
        #pragma unroll
        for (int mi = 0; mi < 3; mi++) {
            #pragma unroll
            for (int hf = 0; hf < 2; hf++) {
                int row = m0 + mi*16 + rq + hf*8;
                float tot = psum[row] + psum[96 + row] + psum[192 + row] + psum[288 + row];
                float inv = 1.0f / tot;
                #pragma unroll
                for (int nj = 0; nj < 3; nj++) {
                    __half2 a2 = __floats2half2_rn(acc[mi][nj][hf*2] * inv,
                                                   acc[mi][nj][hf*2 + 1] * inv);
                    *(__half2*)&sA[row*(APITCH/2) + n0 + nj*8 + c2] = a2;
                }
            }
        }
    }
    CP_WAIT0();          // V fully resident
    __syncthreads();

    // ---- AV: warp tile 48m x 32c, 2 iterations over c halves of 128
    __half* Og = g_Ot + (size_t)bw*HH*CC;
    int cwBase = (warpN & 1) * 32;
    int s0base = (warpN & 1) * 4;

    #pragma unroll
    for (int it = 0; it < 2; it++) {
        int ck = it*2 + (warpN >> 1);
        uint32_t vBase = sb + AOFF_V + (uint32_t)(ck*12288);
        float vacc[3][4][4] = {};
        #pragma unroll
        for (int ks = 0; ks < 6; ks++) {
            uint32_t af[3][4], b04[4], b14[4];
            #pragma unroll
            for (int mi = 0; mi < 3; mi++) {
                int row = m0 + (lane & 15) + mi*16;
                ldsm_x4(af[mi], sb + AOFF_A + (uint32_t)(row*APITCH + ks*32 + (lane >> 4)*16));
            }
            {
                int row = ks*16 + (lane & 15);
                int s0 = s0base + (lane >> 4);
                ldsm_x4t(b04, vBase + (uint32_t)(row*128 + ((s0 ^ swz)*16)));
                ldsm_x4t(b14, vBase + (uint32_t)(row*128 + (((s0 + 2) ^ swz)*16)));
            }
            #pragma unroll
            for (int mi = 0; mi < 3; mi++) {
                mma_h(vacc[mi][0], af[mi], &b04[0]);
                mma_h(vacc[mi][1], af[mi], &b04[2]);
                mma_h(vacc[mi][2], af[mi], &b14[0]);
                mma_h(vacc[mi][3], af[mi], &b14[2]);
            }
        }
        __syncthreads();

        __half* sO = (__half*)(sma + AOFF_O);
        int colW = (warpN >> 1) * 64 + cwBase;
        #pragma unroll
        for (int mi = 0; mi < 3; mi++)
            #pragma unroll
            for (int ni = 0; ni < 4; ni++) {
                int row = m0 + mi*16 + rq, col = colW + ni*8 + c2;
                *(__half2*)&sO[row*OPITCH + col]     = __floats2half2_rn(vacc[mi][ni][0], vacc[mi][ni][1]);
                *(__half2*)&sO[(row+8)*OPITCH + col] = __floats2half2_rn(vacc[mi][ni][2], vacc[mi][ni][3]);
            }
        __syncthreads();

        for (int i = tid; i < 1536; i += 256) {
            int h = i >> 4, c8 = (i & 15) * 8;
            *(uint4*)&Og[(size_t)h*CC + it*128 + c8] = *(uint4*)&sO[h*OPITCH + c8];
        }
    }
}

// ---------------- kernel 3: transpose back + residual (coalesced Ot reads) ---
__global__ __launch_bounds__(256) void out_kernel(const float* __restrict__ x,
                                                  const float* __restrict__ gamma,
                                                  float* __restrict__ out) {
    __shared__ float tile[32][66];
    int c0 = blockIdx.x * 64;
    int w0 = blockIdx.y * 32;
    int bh = blockIdx.z;
    int b = bh / HH, h = bh % HH;
    int tid = threadIdx.x;
    float gm = gamma[0];
    const __half* Ob = g_Ot + (size_t)b * WW * HH * CC;
    {
        int wl = tid >> 3, cs = (tid & 7) * 8;
        uint4 v = *(const uint4*)(Ob + (size_t)((w0 + wl)*HH + h)*CC + c0 + cs);
        __half2* hp = (__half2*)&v;
        #pragma unroll
        for (int i = 0; i < 4; i++) {
            float2 f = __half22float2(hp[i]);
            *(float2*)&tile[wl][cs + i*2] = f;
        }
    }
    __syncthreads();
    {
        int cl = tid >> 2, ws = (tid & 3) * 8;
        size_t base = (size_t)b*CC*PP + (size_t)(c0 + cl)*PP + (size_t)h*WW + w0 + ws;
        float4 x0 = *(const float4*)&x[base];
        float4 x1 = *(const float4*)&x[base + 4];
        float4 o0, o1;
        o0.x = gm*tile[ws+0][cl] + x0.x;
        o0.y = gm*tile[ws+1][cl] + x0.y;
        o0.z = gm*tile[ws+2][cl] + x0.z;
        o0.w = gm*tile[ws+3][cl] + x0.w;
        o1.x = gm*tile[ws+4][cl] + x1.x;
        o1.y = gm*tile[ws+5][cl] + x1.y;
        o1.z = gm*tile[ws+6][cl] + x1.z;
        o1.w = gm*tile[ws+7][cl] + x1.w;
        *(float4*)&out[base]     = o0;
        *(float4*)&out[base + 4] = o1;
    }
}

// ---------------- launcher ---------------------------------------------------
extern "C" void kernel_launch(void* const* d_in, const int* in_sizes, int n_in,
                              void* d_out, int out_size) {
    const float* x     = (const float*)d_in[0];
    const float* Wq    = (const float*)d_in[1];
    const float* bq    = (const float*)d_in[2];
    const float* Wk    = (const float*)d_in[3];
    const float* bk    = (const float*)d_in[4];
    const float* Wv    = (const float*)d_in[5];
    const float* bv    = (const float*)d_in[6];
    const float* gamma = (const float*)d_in[7];
    float* out = (float*)d_out;

    cudaFuncSetAttribute(qkv_mma_kernel, cudaFuncAttributeMaxDynamicSharedMemorySize, QKV_SMEM);
    cudaFuncSetAttribute(attn_mma_kernel, cudaFuncAttributeMaxDynamicSharedMemorySize, ATT_SMEM);

    prep_kernel<<<(JTOT*CC + 255)/256, 256>>>(Wq, bq, Wk, bk, Wv, bv);
    qkv_mma_kernel<<<dim3(PP/64, BB), 256, QKV_SMEM>>>(x);
    attn_mma_kernel<<<dim3(BB*WW), 256, ATT_SMEM>>>();
    out_kernel<<<dim3(CC/64, WW/32, BB*HH), dim3(256)>>>(x, gamma, out);
}